// round 1
// baseline (speedup 1.0000x reference)
#include <cuda_runtime.h>
#include <mma.h>
#include <math.h>

using namespace nvcuda;

#define TOKENS 16384
#define EMB    768
#define NH     12
#define HD     64
#define SLEN   1024
#define BATCH  16
#define MLPD   3072
#define NZ     (BATCH*NH)   // 192 (batch*heads)

// ---------------- scratch (static device globals; no allocation allowed) ----
__device__ float g_h  [TOKENS*EMB];
__device__ float g_q  [TOKENS*EMB];
__device__ float g_k  [TOKENS*EMB];
__device__ float g_v  [TOKENS*EMB];
__device__ float g_ctx[TOKENS*EMB];
__device__ float g_x1 [TOKENS*EMB];
__device__ float g_h2 [TOKENS*EMB];
__device__ float g_m1 [TOKENS*MLPD];
__device__ float g_scores[(size_t)NZ*SLEN*SLEN];   // 805 MB

// ---------------- helpers ---------------------------------------------------
__device__ __forceinline__ float gelu_exact(float x) {
    return 0.5f * x * (1.0f + erff(x * 0.70710678118654752440f));
}

// ---------------- LayerNorm: one block per row of 768 -----------------------
__global__ __launch_bounds__(256) void ln_kernel(
    const float* __restrict__ x, const float* __restrict__ g,
    const float* __restrict__ b, float* __restrict__ y)
{
    size_t row = blockIdx.x;
    const float* xr = x + row * EMB;
    int t = threadIdx.x;
    float v0 = xr[t], v1 = xr[t + 256], v2 = xr[t + 512];
    float s  = v0 + v1 + v2;
    float sq = v0*v0 + v1*v1 + v2*v2;
    __shared__ float red0[8], red1[8];
    #pragma unroll
    for (int o = 16; o; o >>= 1) {
        s  += __shfl_xor_sync(0xFFFFFFFFu, s,  o);
        sq += __shfl_xor_sync(0xFFFFFFFFu, sq, o);
    }
    int warp = t >> 5, lane = t & 31;
    if (lane == 0) { red0[warp] = s; red1[warp] = sq; }
    __syncthreads();
    float ts = 0.f, tq = 0.f;
    #pragma unroll
    for (int i = 0; i < 8; i++) { ts += red0[i]; tq += red1[i]; }
    float mu  = ts * (1.0f / EMB);
    float var = tq * (1.0f / EMB) - mu * mu;
    float rs  = rsqrtf(var + 1e-6f);
    float* yr = y + row * EMB;
    yr[t]       = (v0 - mu) * rs * g[t]       + b[t];
    yr[t + 256] = (v1 - mu) * rs * g[t + 256] + b[t + 256];
    yr[t + 512] = (v2 - mu) * rs * g[t + 512] + b[t + 512];
}

// ---------------- generic TF32 GEMM: C = A(MxK) * B(KxN) + bias (+epi) ------
// EPI: 0 = bias only, 1 = bias + exact GELU, 2 = bias + residual add
#define BM 128
#define BN 128
#define BK 32

template<int EPI>
__global__ __launch_bounds__(256) void gemm_tf32_kernel(
    const float* __restrict__ A, const float* __restrict__ B,
    const float* __restrict__ bias, const float* __restrict__ R,
    float* __restrict__ C, int M, int N, int K)
{
    __shared__ float As[BM][BK + 4];        // ldm 36 (144B, 16B-mult)
    __shared__ float Bs[BK][BN + 4];        // ldm 132 (528B, 16B-mult)
    __shared__ float stage[8][16][20];      // ldm 20 (80B, 16B-mult)

    int tid = threadIdx.x;
    int warp = tid >> 5, lane = tid & 31;
    int wr = warp >> 2, wc = warp & 3;      // 2 x 4 warp grid, warp tile 64x32
    int rowBase = blockIdx.y * BM;
    int colBase = blockIdx.x * BN;

    wmma::fragment<wmma::accumulator, 16, 16, 8, float> acc[4][2];
    #pragma unroll
    for (int f = 0; f < 4; f++)
        #pragma unroll
        for (int g = 0; g < 2; g++) wmma::fill_fragment(acc[f][g], 0.0f);

    for (int k0 = 0; k0 < K; k0 += BK) {
        #pragma unroll
        for (int i = 0; i < 4; i++) {
            int idx = tid + i * 256;
            int r = idx >> 3, c = (idx & 7) << 2;
            float4 tv = *(const float4*)(A + (size_t)(rowBase + r) * K + k0 + c);
            As[r][c] = tv.x; As[r][c+1] = tv.y; As[r][c+2] = tv.z; As[r][c+3] = tv.w;
        }
        #pragma unroll
        for (int i = 0; i < 4; i++) {
            int idx = tid + i * 256;
            int r = idx >> 5, c = (idx & 31) << 2;
            float4 tv = *(const float4*)(B + (size_t)(k0 + r) * N + colBase + c);
            Bs[r][c] = tv.x; Bs[r][c+1] = tv.y; Bs[r][c+2] = tv.z; Bs[r][c+3] = tv.w;
        }
        __syncthreads();
        #pragma unroll
        for (int kk = 0; kk < BK; kk += 8) {
            wmma::fragment<wmma::matrix_a, 16, 16, 8, wmma::precision::tf32, wmma::row_major> af[4];
            wmma::fragment<wmma::matrix_b, 16, 16, 8, wmma::precision::tf32, wmma::row_major> bf[2];
            #pragma unroll
            for (int f = 0; f < 4; f++) {
                wmma::load_matrix_sync(af[f], &As[wr * 64 + f * 16][kk], BK + 4);
                #pragma unroll
                for (int e = 0; e < af[f].num_elements; e++)
                    af[f].x[e] = wmma::__float_to_tf32(af[f].x[e]);
            }
            #pragma unroll
            for (int g = 0; g < 2; g++) {
                wmma::load_matrix_sync(bf[g], &Bs[kk][wc * 32 + g * 16], BN + 4);
                #pragma unroll
                for (int e = 0; e < bf[g].num_elements; e++)
                    bf[g].x[e] = wmma::__float_to_tf32(bf[g].x[e]);
            }
            #pragma unroll
            for (int f = 0; f < 4; f++)
                #pragma unroll
                for (int g = 0; g < 2; g++)
                    wmma::mma_sync(acc[f][g], af[f], bf[g], acc[f][g]);
        }
        __syncthreads();
    }

    // epilogue via per-warp smem staging (bias / gelu / residual)
    #pragma unroll
    for (int f = 0; f < 4; f++) {
        #pragma unroll
        for (int g = 0; g < 2; g++) {
            wmma::store_matrix_sync(&stage[warp][0][0], acc[f][g], 20, wmma::mem_row_major);
            __syncwarp();
            int row0 = rowBase + wr * 64 + f * 16;
            int col0 = colBase + wc * 32 + g * 16;
            #pragma unroll
            for (int j = 0; j < 8; j++) {
                int e = lane + j * 32;
                int r = e >> 4, c = e & 15;
                float val = stage[warp][r][c] + bias[col0 + c];
                if (EPI == 1) val = gelu_exact(val);
                size_t oidx = (size_t)(row0 + r) * N + (col0 + c);
                if (EPI == 2) val += R[oidx];
                C[oidx] = val;
            }
            __syncwarp();
        }
    }
}

// ---------------- attention scores: S[z] = Q[z] * K[z]^T / 8 ----------------
// per z=(b,h): Q rows [1024 x 64] stride EMB; grid (8, 8, 192)
__global__ __launch_bounds__(256) void attn_scores_kernel(
    const float* __restrict__ Q, const float* __restrict__ Km,
    float* __restrict__ S)
{
    __shared__ float As[128][36];
    __shared__ float Bs[128][36];
    int z = blockIdx.z, b = z / NH, h = z % NH;
    const float* Qb = Q  + (size_t)b * SLEN * EMB + h * HD;
    const float* Kb = Km + (size_t)b * SLEN * EMB + h * HD;
    float* Sb = S + (size_t)z * SLEN * SLEN;

    int tid = threadIdx.x, warp = tid >> 5;
    int wr = warp >> 2, wc = warp & 3;
    int rowBase = blockIdx.y * 128, colBase = blockIdx.x * 128;

    wmma::fragment<wmma::accumulator, 16, 16, 8, float> acc[4][2];
    #pragma unroll
    for (int f = 0; f < 4; f++)
        #pragma unroll
        for (int g = 0; g < 2; g++) wmma::fill_fragment(acc[f][g], 0.0f);

    #pragma unroll
    for (int k0 = 0; k0 < HD; k0 += 32) {
        #pragma unroll
        for (int i = 0; i < 4; i++) {
            int idx = tid + i * 256;
            int r = idx >> 3, c = (idx & 7) << 2;
            float4 tv = *(const float4*)(Qb + (size_t)(rowBase + r) * EMB + k0 + c);
            As[r][c] = tv.x; As[r][c+1] = tv.y; As[r][c+2] = tv.z; As[r][c+3] = tv.w;
        }
        #pragma unroll
        for (int i = 0; i < 4; i++) {
            int idx = tid + i * 256;
            int r = idx >> 3, c = (idx & 7) << 2;
            float4 tv = *(const float4*)(Kb + (size_t)(colBase + r) * EMB + k0 + c);
            Bs[r][c] = tv.x; Bs[r][c+1] = tv.y; Bs[r][c+2] = tv.z; Bs[r][c+3] = tv.w;
        }
        __syncthreads();
        #pragma unroll
        for (int kk = 0; kk < 32; kk += 8) {
            wmma::fragment<wmma::matrix_a, 16, 16, 8, wmma::precision::tf32, wmma::row_major> af[4];
            wmma::fragment<wmma::matrix_b, 16, 16, 8, wmma::precision::tf32, wmma::col_major> bf[2];
            #pragma unroll
            for (int f = 0; f < 4; f++) {
                wmma::load_matrix_sync(af[f], &As[wr * 64 + f * 16][kk], 36);
                #pragma unroll
                for (int e = 0; e < af[f].num_elements; e++)
                    af[f].x[e] = wmma::__float_to_tf32(af[f].x[e]);
            }
            #pragma unroll
            for (int g = 0; g < 2; g++) {
                wmma::load_matrix_sync(bf[g], &Bs[wc * 32 + g * 16][kk], 36);
                #pragma unroll
                for (int e = 0; e < bf[g].num_elements; e++)
                    bf[g].x[e] = wmma::__float_to_tf32(bf[g].x[e]);
            }
            #pragma unroll
            for (int f = 0; f < 4; f++)
                #pragma unroll
                for (int g = 0; g < 2; g++)
                    wmma::mma_sync(acc[f][g], af[f], bf[g], acc[f][g]);
        }
        __syncthreads();
    }
    #pragma unroll
    for (int f = 0; f < 4; f++)
        #pragma unroll
        for (int g = 0; g < 2; g++) {
            #pragma unroll
            for (int e = 0; e < acc[f][g].num_elements; e++) acc[f][g].x[e] *= 0.125f;
            float* dst = Sb + (size_t)(rowBase + wr * 64 + f * 16) * SLEN
                            + colBase + wc * 32 + g * 16;
            wmma::store_matrix_sync(dst, acc[f][g], SLEN, wmma::mem_row_major);
        }
}

// ---------------- softmax: one block per row of 1024 ------------------------
__global__ __launch_bounds__(256) void softmax_kernel(float* __restrict__ S)
{
    float* p = S + (size_t)blockIdx.x * SLEN;
    int t = threadIdx.x, warp = t >> 5, lane = t & 31;
    float4 v = *(float4*)(p + t * 4);
    __shared__ float red[8];

    float m = fmaxf(fmaxf(v.x, v.y), fmaxf(v.z, v.w));
    #pragma unroll
    for (int o = 16; o; o >>= 1) m = fmaxf(m, __shfl_xor_sync(0xFFFFFFFFu, m, o));
    if (lane == 0) red[warp] = m;
    __syncthreads();
    float bm = red[0];
    #pragma unroll
    for (int i = 1; i < 8; i++) bm = fmaxf(bm, red[i]);
    __syncthreads();

    v.x = expf(v.x - bm); v.y = expf(v.y - bm);
    v.z = expf(v.z - bm); v.w = expf(v.w - bm);
    float s = v.x + v.y + v.z + v.w;
    #pragma unroll
    for (int o = 16; o; o >>= 1) s += __shfl_xor_sync(0xFFFFFFFFu, s, o);
    if (lane == 0) red[warp] = s;
    __syncthreads();
    float bs = 0.f;
    #pragma unroll
    for (int i = 0; i < 8; i++) bs += red[i];
    float inv = 1.0f / bs;
    v.x *= inv; v.y *= inv; v.z *= inv; v.w *= inv;
    *(float4*)(p + t * 4) = v;
}

// ---------------- PV: ctx[z] = P[z](1024x1024) * V[z](1024x64) --------------
// grid (1, 8, 192); output strided into [B,S,H,D]
__global__ __launch_bounds__(256) void attn_pv_kernel(
    const float* __restrict__ P, const float* __restrict__ V,
    float* __restrict__ Ctx)
{
    __shared__ float As[128][36];
    __shared__ float Bs[32][68];    // ldm 68 (272B, 16B-mult)
    int z = blockIdx.z, b = z / NH, h = z % NH;
    const float* Pb = P + (size_t)z * SLEN * SLEN;
    const float* Vb = V + (size_t)b * SLEN * EMB + h * HD;
    float* Cb = Ctx + (size_t)b * SLEN * EMB + h * HD;

    int tid = threadIdx.x, warp = tid >> 5;
    int wr = warp >> 1, wc = warp & 1;     // 4 x 2 warp grid, warp tile 32x32
    int rowBase = blockIdx.y * 128;

    wmma::fragment<wmma::accumulator, 16, 16, 8, float> acc[2][2];
    #pragma unroll
    for (int f = 0; f < 2; f++)
        #pragma unroll
        for (int g = 0; g < 2; g++) wmma::fill_fragment(acc[f][g], 0.0f);

    for (int k0 = 0; k0 < SLEN; k0 += 32) {
        #pragma unroll
        for (int i = 0; i < 4; i++) {
            int idx = tid + i * 256;
            int r = idx >> 3, c = (idx & 7) << 2;
            float4 tv = *(const float4*)(Pb + (size_t)(rowBase + r) * SLEN + k0 + c);
            As[r][c] = tv.x; As[r][c+1] = tv.y; As[r][c+2] = tv.z; As[r][c+3] = tv.w;
        }
        #pragma unroll
        for (int i = 0; i < 2; i++) {
            int idx = tid + i * 256;
            int r = idx >> 4, c = (idx & 15) << 2;
            float4 tv = *(const float4*)(Vb + (size_t)(k0 + r) * EMB + c);
            Bs[r][c] = tv.x; Bs[r][c+1] = tv.y; Bs[r][c+2] = tv.z; Bs[r][c+3] = tv.w;
        }
        __syncthreads();
        #pragma unroll
        for (int kk = 0; kk < 32; kk += 8) {
            wmma::fragment<wmma::matrix_a, 16, 16, 8, wmma::precision::tf32, wmma::row_major> af[2];
            wmma::fragment<wmma::matrix_b, 16, 16, 8, wmma::precision::tf32, wmma::row_major> bf[2];
            #pragma unroll
            for (int f = 0; f < 2; f++) {
                wmma::load_matrix_sync(af[f], &As[wr * 32 + f * 16][kk], 36);
                #pragma unroll
                for (int e = 0; e < af[f].num_elements; e++)
                    af[f].x[e] = wmma::__float_to_tf32(af[f].x[e]);
            }
            #pragma unroll
            for (int g = 0; g < 2; g++) {
                wmma::load_matrix_sync(bf[g], &Bs[kk][wc * 32 + g * 16], 68);
                #pragma unroll
                for (int e = 0; e < bf[g].num_elements; e++)
                    bf[g].x[e] = wmma::__float_to_tf32(bf[g].x[e]);
            }
            #pragma unroll
            for (int f = 0; f < 2; f++)
                #pragma unroll
                for (int g = 0; g < 2; g++)
                    wmma::mma_sync(acc[f][g], af[f], bf[g], acc[f][g]);
        }
        __syncthreads();
    }
    #pragma unroll
    for (int f = 0; f < 2; f++)
        #pragma unroll
        for (int g = 0; g < 2; g++) {
            float* dst = Cb + (size_t)(rowBase + wr * 32 + f * 16) * EMB
                            + wc * 32 + g * 16;
            wmma::store_matrix_sync(dst, acc[f][g], EMB, wmma::mem_row_major);
        }
}

// ---------------- launch ----------------------------------------------------
extern "C" void kernel_launch(void* const* d_in, const int* in_sizes, int n_in,
                              void* d_out, int out_size)
{
    const float* x     = (const float*)d_in[0];
    const float* ln1_g = (const float*)d_in[1];
    const float* ln1_b = (const float*)d_in[2];
    const float* Wq    = (const float*)d_in[3];
    const float* bq    = (const float*)d_in[4];
    const float* Wk    = (const float*)d_in[5];
    const float* bk    = (const float*)d_in[6];
    const float* Wv    = (const float*)d_in[7];
    const float* bv    = (const float*)d_in[8];
    const float* Wo    = (const float*)d_in[9];
    const float* bo    = (const float*)d_in[10];
    const float* ln2_g = (const float*)d_in[11];
    const float* ln2_b = (const float*)d_in[12];
    const float* W1    = (const float*)d_in[13];
    const float* b1    = (const float*)d_in[14];
    const float* W2    = (const float*)d_in[15];
    const float* b2    = (const float*)d_in[16];
    float* out = (float*)d_out;

    float *p_h, *p_q, *p_k, *p_v, *p_ctx, *p_x1, *p_h2, *p_m1, *p_sc;
    cudaGetSymbolAddress((void**)&p_h,   g_h);
    cudaGetSymbolAddress((void**)&p_q,   g_q);
    cudaGetSymbolAddress((void**)&p_k,   g_k);
    cudaGetSymbolAddress((void**)&p_v,   g_v);
    cudaGetSymbolAddress((void**)&p_ctx, g_ctx);
    cudaGetSymbolAddress((void**)&p_x1,  g_x1);
    cudaGetSymbolAddress((void**)&p_h2,  g_h2);
    cudaGetSymbolAddress((void**)&p_m1,  g_m1);
    cudaGetSymbolAddress((void**)&p_sc,  g_scores);

    dim3 gProj(EMB / BN, TOKENS / BM);      // (6, 128)
    dim3 gMlp1(MLPD / BN, TOKENS / BM);     // (24, 128)

    // LN1
    ln_kernel<<<TOKENS, 256>>>(x, ln1_g, ln1_b, p_h);
    // QKV projections
    gemm_tf32_kernel<0><<<gProj, 256>>>(p_h, Wq, bq, nullptr, p_q, TOKENS, EMB, EMB);
    gemm_tf32_kernel<0><<<gProj, 256>>>(p_h, Wk, bk, nullptr, p_k, TOKENS, EMB, EMB);
    gemm_tf32_kernel<0><<<gProj, 256>>>(p_h, Wv, bv, nullptr, p_v, TOKENS, EMB, EMB);
    // attention
    attn_scores_kernel<<<dim3(8, 8, NZ), 256>>>(p_q, p_k, p_sc);
    softmax_kernel<<<NZ * SLEN, 256>>>(p_sc);
    attn_pv_kernel<<<dim3(1, 8, NZ), 256>>>(p_sc, p_v, p_ctx);
    // O projection + residual(x) -> x1
    gemm_tf32_kernel<2><<<gProj, 256>>>(p_ctx, Wo, bo, x, p_x1, TOKENS, EMB, EMB);
    // LN2
    ln_kernel<<<TOKENS, 256>>>(p_x1, ln2_g, ln2_b, p_h2);
    // MLP
    gemm_tf32_kernel<1><<<gMlp1, 256>>>(p_h2, W1, b1, nullptr, p_m1, TOKENS, MLPD, EMB);
    gemm_tf32_kernel<2><<<gProj, 256>>>(p_m1, W2, b2, p_x1, out, TOKENS, EMB, MLPD);
}

// round 3
// speedup vs baseline: 1.1617x; 1.1617x over previous
#include <cuda_runtime.h>
#include <cstdint>
#include <mma.h>
#include <math.h>

using namespace nvcuda;

#define TOKENS 16384
#define EMB    768
#define NH     12
#define HD     64
#define SLEN   1024
#define BATCH  16
#define MLPD   3072
#define NZ     (BATCH*NH)   // 192

// ---------------- scratch -----------------------------------------------
__device__ float g_h  [TOKENS*EMB];
__device__ float g_q  [TOKENS*EMB];
__device__ float g_k  [TOKENS*EMB];
__device__ float g_v  [TOKENS*EMB];
__device__ float g_ctx[TOKENS*EMB];
__device__ float g_x1 [TOKENS*EMB];
__device__ float g_h2 [TOKENS*EMB];
__device__ float g_m1 [TOKENS*MLPD];
__device__ float g_scores[(size_t)NZ*SLEN*SLEN];

// ---------------- helpers -----------------------------------------------
__device__ __forceinline__ float gelu_exact(float x) {
    return 0.5f * x * (1.0f + erff(x * 0.70710678118654752440f));
}

__device__ __forceinline__ void cp16(float* dst, const float* src) {
    unsigned int s = (unsigned int)__cvta_generic_to_shared(dst);
    asm volatile("cp.async.cg.shared.global [%0], [%1], 16;\n" :: "r"(s), "l"(src));
}
#define CP_COMMIT()  asm volatile("cp.async.commit_group;\n" ::)
#define CP_WAIT(N)   asm volatile("cp.async.wait_group %0;\n" :: "n"(N))

// ---------------- LayerNorm ----------------------------------------------
__global__ __launch_bounds__(256) void ln_kernel(
    const float* __restrict__ x, const float* __restrict__ g,
    const float* __restrict__ b, float* __restrict__ y)
{
    size_t row = blockIdx.x;
    const float* xr = x + row * EMB;
    int t = threadIdx.x;
    float v0 = xr[t], v1 = xr[t + 256], v2 = xr[t + 512];
    float s  = v0 + v1 + v2;
    float sq = v0*v0 + v1*v1 + v2*v2;
    __shared__ float red0[8], red1[8];
    #pragma unroll
    for (int o = 16; o; o >>= 1) {
        s  += __shfl_xor_sync(0xFFFFFFFFu, s,  o);
        sq += __shfl_xor_sync(0xFFFFFFFFu, sq, o);
    }
    int warp = t >> 5, lane = t & 31;
    if (lane == 0) { red0[warp] = s; red1[warp] = sq; }
    __syncthreads();
    float ts = 0.f, tq = 0.f;
    #pragma unroll
    for (int i = 0; i < 8; i++) { ts += red0[i]; tq += red1[i]; }
    float mu  = ts * (1.0f / EMB);
    float var = tq * (1.0f / EMB) - mu * mu;
    float rs  = rsqrtf(var + 1e-6f);
    float* yr = y + row * EMB;
    yr[t]       = (v0 - mu) * rs * g[t]       + b[t];
    yr[t + 256] = (v1 - mu) * rs * g[t + 256] + b[t + 256];
    yr[t + 512] = (v2 - mu) * rs * g[t + 512] + b[t + 512];
}

// ---------------- pipelined TF32 GEMM: C = A*B + bias (+epi) -------------
// EPI: 0 bias, 1 bias+gelu, 2 bias+residual
// dynamic smem: As[2] 128x36, Bs[2] 32x132  (70656 bytes)
#define GEMM_SMEM 70656

template<int EPI>
__global__ __launch_bounds__(256, 2) void gemm_tf32_kernel(
    const float* __restrict__ A, const float* __restrict__ B,
    const float* __restrict__ bias, const float* __restrict__ R,
    float* __restrict__ C, int M, int N, int K)
{
    extern __shared__ float sm[];
    float* Asb[2] = { sm,        sm + 4608 };
    float* Bsb[2] = { sm + 9216, sm + 13440 };

    int tid = threadIdx.x;
    int warp = tid >> 5, lane = tid & 31;
    int wr = warp >> 2, wc = warp & 3;          // 2x4 warps, warp tile 64x32
    int rowBase = blockIdx.y * 128;
    int colBase = blockIdx.x * 128;

    wmma::fragment<wmma::accumulator, 16, 16, 8, float> acc[4][2];
    #pragma unroll
    for (int f = 0; f < 4; f++)
        #pragma unroll
        for (int g = 0; g < 2; g++) wmma::fill_fragment(acc[f][g], 0.0f);

    auto load_stage = [&](int buf, int k0) {
        float* As = Asb[buf];
        float* Bs = Bsb[buf];
        #pragma unroll
        for (int i = 0; i < 4; i++) {
            int idx = tid + i * 256;
            int r = idx >> 3, c = (idx & 7) << 2;
            cp16(As + r * 36 + c, A + (size_t)(rowBase + r) * K + k0 + c);
        }
        #pragma unroll
        for (int i = 0; i < 4; i++) {
            int idx = tid + i * 256;
            int r = idx >> 5, c = (idx & 31) << 2;
            cp16(Bs + r * 132 + c, B + (size_t)(k0 + r) * N + colBase + c);
        }
    };

    load_stage(0, 0);
    CP_COMMIT();

    int buf = 0;
    for (int k0 = 0; k0 < K; k0 += 32) {
        if (k0 + 32 < K) {
            load_stage(buf ^ 1, k0 + 32);
            CP_COMMIT();
            CP_WAIT(1);
        } else {
            CP_WAIT(0);
        }
        __syncthreads();
        float* As = Asb[buf];
        float* Bs = Bsb[buf];
        #pragma unroll
        for (int kk = 0; kk < 32; kk += 8) {
            wmma::fragment<wmma::matrix_a, 16, 16, 8, wmma::precision::tf32, wmma::row_major> af[4];
            wmma::fragment<wmma::matrix_b, 16, 16, 8, wmma::precision::tf32, wmma::row_major> bf[2];
            #pragma unroll
            for (int f = 0; f < 4; f++)
                wmma::load_matrix_sync(af[f], As + (wr * 64 + f * 16) * 36 + kk, 36);
            #pragma unroll
            for (int g = 0; g < 2; g++)
                wmma::load_matrix_sync(bf[g], Bs + kk * 132 + wc * 32 + g * 16, 132);
            #pragma unroll
            for (int f = 0; f < 4; f++)
                #pragma unroll
                for (int g = 0; g < 2; g++)
                    wmma::mma_sync(acc[f][g], af[f], bf[g], acc[f][g]);
        }
        __syncthreads();
        buf ^= 1;
    }

    // epilogue: reuse smem for staging (16x20 per warp)
    float* stage = sm + warp * 320;
    #pragma unroll
    for (int f = 0; f < 4; f++) {
        #pragma unroll
        for (int g = 0; g < 2; g++) {
            wmma::store_matrix_sync(stage, acc[f][g], 20, wmma::mem_row_major);
            __syncwarp();
            int row0 = rowBase + wr * 64 + f * 16;
            int col0 = colBase + wc * 32 + g * 16;
            #pragma unroll
            for (int j = 0; j < 8; j++) {
                int e = lane + j * 32;
                int r = e >> 4, c = e & 15;
                float val = stage[r * 20 + c] + bias[col0 + c];
                if (EPI == 1) val = gelu_exact(val);
                size_t oidx = (size_t)(row0 + r) * N + (col0 + c);
                if (EPI == 2) val += R[oidx];
                C[oidx] = val;
            }
            __syncwarp();
        }
    }
}

// ---------------- attention scores: S[z] = Q[z] * K[z]^T / 8 --------------
__global__ __launch_bounds__(256) void attn_scores_kernel(
    const float* __restrict__ Q, const float* __restrict__ Km,
    float* __restrict__ S)
{
    __shared__ float As[128][36];
    __shared__ float Bs[128][36];
    int z = blockIdx.z, b = z / NH, h = z % NH;
    const float* Qb = Q  + (size_t)b * SLEN * EMB + h * HD;
    const float* Kb = Km + (size_t)b * SLEN * EMB + h * HD;
    float* Sb = S + (size_t)z * SLEN * SLEN;

    int tid = threadIdx.x, warp = tid >> 5;
    int wr = warp >> 2, wc = warp & 3;
    int rowBase = blockIdx.y * 128, colBase = blockIdx.x * 128;

    wmma::fragment<wmma::accumulator, 16, 16, 8, float> acc[4][2];
    #pragma unroll
    for (int f = 0; f < 4; f++)
        #pragma unroll
        for (int g = 0; g < 2; g++) wmma::fill_fragment(acc[f][g], 0.0f);

    #pragma unroll
    for (int k0 = 0; k0 < HD; k0 += 32) {
        #pragma unroll
        for (int i = 0; i < 4; i++) {
            int idx = tid + i * 256;
            int r = idx >> 3, c = (idx & 7) << 2;
            float4 tv = *(const float4*)(Qb + (size_t)(rowBase + r) * EMB + k0 + c);
            As[r][c] = tv.x; As[r][c+1] = tv.y; As[r][c+2] = tv.z; As[r][c+3] = tv.w;
        }
        #pragma unroll
        for (int i = 0; i < 4; i++) {
            int idx = tid + i * 256;
            int r = idx >> 3, c = (idx & 7) << 2;
            float4 tv = *(const float4*)(Kb + (size_t)(colBase + r) * EMB + k0 + c);
            Bs[r][c] = tv.x; Bs[r][c+1] = tv.y; Bs[r][c+2] = tv.z; Bs[r][c+3] = tv.w;
        }
        __syncthreads();
        #pragma unroll
        for (int kk = 0; kk < 32; kk += 8) {
            wmma::fragment<wmma::matrix_a, 16, 16, 8, wmma::precision::tf32, wmma::row_major> af[4];
            wmma::fragment<wmma::matrix_b, 16, 16, 8, wmma::precision::tf32, wmma::col_major> bf[2];
            #pragma unroll
            for (int f = 0; f < 4; f++)
                wmma::load_matrix_sync(af[f], &As[wr * 64 + f * 16][kk], 36);
            #pragma unroll
            for (int g = 0; g < 2; g++)
                wmma::load_matrix_sync(bf[g], &Bs[wc * 32 + g * 16][kk], 36);
            #pragma unroll
            for (int f = 0; f < 4; f++)
                #pragma unroll
                for (int g = 0; g < 2; g++)
                    wmma::mma_sync(acc[f][g], af[f], bf[g], acc[f][g]);
        }
        __syncthreads();
    }
    #pragma unroll
    for (int f = 0; f < 4; f++)
        #pragma unroll
        for (int g = 0; g < 2; g++) {
            #pragma unroll
            for (int e = 0; e < acc[f][g].num_elements; e++) acc[f][g].x[e] *= 0.125f;
            float* dst = Sb + (size_t)(rowBase + wr * 64 + f * 16) * SLEN
                            + colBase + wc * 32 + g * 16;
            wmma::store_matrix_sync(dst, acc[f][g], SLEN, wmma::mem_row_major);
        }
}

// ---------------- softmax -------------------------------------------------
__global__ __launch_bounds__(256) void softmax_kernel(float* __restrict__ S)
{
    float* p = S + (size_t)blockIdx.x * SLEN;
    int t = threadIdx.x, warp = t >> 5, lane = t & 31;
    float4 v = *(float4*)(p + t * 4);
    __shared__ float red[8];

    float m = fmaxf(fmaxf(v.x, v.y), fmaxf(v.z, v.w));
    #pragma unroll
    for (int o = 16; o; o >>= 1) m = fmaxf(m, __shfl_xor_sync(0xFFFFFFFFu, m, o));
    if (lane == 0) red[warp] = m;
    __syncthreads();
    float bm = red[0];
    #pragma unroll
    for (int i = 1; i < 8; i++) bm = fmaxf(bm, red[i]);
    __syncthreads();

    v.x = expf(v.x - bm); v.y = expf(v.y - bm);
    v.z = expf(v.z - bm); v.w = expf(v.w - bm);
    float s = v.x + v.y + v.z + v.w;
    #pragma unroll
    for (int o = 16; o; o >>= 1) s += __shfl_xor_sync(0xFFFFFFFFu, s, o);
    if (lane == 0) red[warp] = s;
    __syncthreads();
    float bs = 0.f;
    #pragma unroll
    for (int i = 0; i < 8; i++) bs += red[i];
    float inv = 1.0f / bs;
    v.x *= inv; v.y *= inv; v.z *= inv; v.w *= inv;
    *(float4*)(p + t * 4) = v;
}

// ---------------- PV (pipelined): ctx = P(1024x1024) * V(1024x64) ---------
// dynamic smem: As[2] 128x36, Bs[2] 32x68  (54272 bytes)
#define PV_SMEM 54272

__global__ __launch_bounds__(256, 2) void attn_pv_kernel(
    const float* __restrict__ P, const float* __restrict__ V,
    float* __restrict__ Ctx)
{
    extern __shared__ float sm[];
    float* Asb[2] = { sm,        sm + 4608 };
    float* Bsb[2] = { sm + 9216, sm + 11392 };

    int z = blockIdx.z, b = z / NH, h = z % NH;
    const float* Pb = P + (size_t)z * SLEN * SLEN;
    const float* Vb = V + (size_t)b * SLEN * EMB + h * HD;
    float* Cb = Ctx + (size_t)b * SLEN * EMB + h * HD;

    int tid = threadIdx.x, warp = tid >> 5;
    int wr = warp >> 1, wc = warp & 1;      // 4x2 warps, warp tile 32x32
    int rowBase = blockIdx.y * 128;

    wmma::fragment<wmma::accumulator, 16, 16, 8, float> acc[2][2];
    #pragma unroll
    for (int f = 0; f < 2; f++)
        #pragma unroll
        for (int g = 0; g < 2; g++) wmma::fill_fragment(acc[f][g], 0.0f);

    auto load_stage = [&](int buf, int k0) {
        float* As = Asb[buf];
        float* Bs = Bsb[buf];
        #pragma unroll
        for (int i = 0; i < 4; i++) {
            int idx = tid + i * 256;
            int r = idx >> 3, c = (idx & 7) << 2;
            cp16(As + r * 36 + c, Pb + (size_t)(rowBase + r) * SLEN + k0 + c);
        }
        #pragma unroll
        for (int i = 0; i < 2; i++) {
            int idx = tid + i * 256;
            int r = idx >> 4, c = (idx & 15) << 2;
            cp16(Bs + r * 68 + c, Vb + (size_t)(k0 + r) * EMB + c);
        }
    };

    load_stage(0, 0);
    CP_COMMIT();

    int buf = 0;
    for (int k0 = 0; k0 < SLEN; k0 += 32) {
        if (k0 + 32 < SLEN) {
            load_stage(buf ^ 1, k0 + 32);
            CP_COMMIT();
            CP_WAIT(1);
        } else {
            CP_WAIT(0);
        }
        __syncthreads();
        float* As = Asb[buf];
        float* Bs = Bsb[buf];
        #pragma unroll
        for (int kk = 0; kk < 32; kk += 8) {
            wmma::fragment<wmma::matrix_a, 16, 16, 8, wmma::precision::tf32, wmma::row_major> af[2];
            wmma::fragment<wmma::matrix_b, 16, 16, 8, wmma::precision::tf32, wmma::row_major> bf[2];
            #pragma unroll
            for (int f = 0; f < 2; f++)
                wmma::load_matrix_sync(af[f], As + (wr * 32 + f * 16) * 36 + kk, 36);
            #pragma unroll
            for (int g = 0; g < 2; g++)
                wmma::load_matrix_sync(bf[g], Bs + kk * 68 + wc * 32 + g * 16, 68);
            #pragma unroll
            for (int f = 0; f < 2; f++)
                #pragma unroll
                for (int g = 0; g < 2; g++)
                    wmma::mma_sync(acc[f][g], af[f], bf[g], acc[f][g]);
        }
        __syncthreads();
        buf ^= 1;
    }
    #pragma unroll
    for (int f = 0; f < 2; f++)
        #pragma unroll
        for (int g = 0; g < 2; g++) {
            float* dst = Cb + (size_t)(rowBase + wr * 32 + f * 16) * EMB
                            + wc * 32 + g * 16;
            wmma::store_matrix_sync(dst, acc[f][g], EMB, wmma::mem_row_major);
        }
}

// ---------------- launch --------------------------------------------------
extern "C" void kernel_launch(void* const* d_in, const int* in_sizes, int n_in,
                              void* d_out, int out_size)
{
    const float* x     = (const float*)d_in[0];
    const float* ln1_g = (const float*)d_in[1];
    const float* ln1_b = (const float*)d_in[2];
    const float* Wq    = (const float*)d_in[3];
    const float* bq    = (const float*)d_in[4];
    const float* Wk    = (const float*)d_in[5];
    const float* bk    = (const float*)d_in[6];
    const float* Wv    = (const float*)d_in[7];
    const float* bv    = (const float*)d_in[8];
    const float* Wo    = (const float*)d_in[9];
    const float* bo    = (const float*)d_in[10];
    const float* ln2_g = (const float*)d_in[11];
    const float* ln2_b = (const float*)d_in[12];
    const float* W1    = (const float*)d_in[13];
    const float* b1    = (const float*)d_in[14];
    const float* W2    = (const float*)d_in[15];
    const float* b2    = (const float*)d_in[16];
    float* out = (float*)d_out;

    float *p_h, *p_q, *p_k, *p_v, *p_ctx, *p_x1, *p_h2, *p_m1, *p_sc;
    cudaGetSymbolAddress((void**)&p_h,   g_h);
    cudaGetSymbolAddress((void**)&p_q,   g_q);
    cudaGetSymbolAddress((void**)&p_k,   g_k);
    cudaGetSymbolAddress((void**)&p_v,   g_v);
    cudaGetSymbolAddress((void**)&p_ctx, g_ctx);
    cudaGetSymbolAddress((void**)&p_x1,  g_x1);
    cudaGetSymbolAddress((void**)&p_h2,  g_h2);
    cudaGetSymbolAddress((void**)&p_m1,  g_m1);
    cudaGetSymbolAddress((void**)&p_sc,  g_scores);

    cudaFuncSetAttribute(gemm_tf32_kernel<0>, cudaFuncAttributeMaxDynamicSharedMemorySize, GEMM_SMEM);
    cudaFuncSetAttribute(gemm_tf32_kernel<1>, cudaFuncAttributeMaxDynamicSharedMemorySize, GEMM_SMEM);
    cudaFuncSetAttribute(gemm_tf32_kernel<2>, cudaFuncAttributeMaxDynamicSharedMemorySize, GEMM_SMEM);
    cudaFuncSetAttribute(attn_pv_kernel,      cudaFuncAttributeMaxDynamicSharedMemorySize, PV_SMEM);

    dim3 gProj(EMB / 128, TOKENS / 128);    // (6, 128)
    dim3 gMlp1(MLPD / 128, TOKENS / 128);   // (24, 128)

    ln_kernel<<<TOKENS, 256>>>(x, ln1_g, ln1_b, p_h);
    gemm_tf32_kernel<0><<<gProj, 256, GEMM_SMEM>>>(p_h, Wq, bq, nullptr, p_q, TOKENS, EMB, EMB);
    gemm_tf32_kernel<0><<<gProj, 256, GEMM_SMEM>>>(p_h, Wk, bk, nullptr, p_k, TOKENS, EMB, EMB);
    gemm_tf32_kernel<0><<<gProj, 256, GEMM_SMEM>>>(p_h, Wv, bv, nullptr, p_v, TOKENS, EMB, EMB);
    attn_scores_kernel<<<dim3(8, 8, NZ), 256>>>(p_q, p_k, p_sc);
    softmax_kernel<<<NZ * SLEN, 256>>>(p_sc);
    attn_pv_kernel<<<dim3(1, 8, NZ), 256, PV_SMEM>>>(p_sc, p_v, p_ctx);
    gemm_tf32_kernel<2><<<gProj, 256, GEMM_SMEM>>>(p_ctx, Wo, bo, x, p_x1, TOKENS, EMB, EMB);
    ln_kernel<<<TOKENS, 256>>>(p_x1, ln2_g, ln2_b, p_h2);
    gemm_tf32_kernel<1><<<gMlp1, 256, GEMM_SMEM>>>(p_h2, W1, b1, nullptr, p_m1, TOKENS, MLPD, EMB);
    gemm_tf32_kernel<2><<<gProj, 256, GEMM_SMEM>>>(p_m1, W2, b2, p_x1, out, TOKENS, EMB, MLPD);
}

// round 5
// speedup vs baseline: 1.3205x; 1.1366x over previous
#include <cuda_runtime.h>
#include <cstdint>
#include <mma.h>
#include <math.h>

using namespace nvcuda;

#define TOKENS 16384
#define EMB    768
#define NH     12
#define HD     64
#define SLEN   1024
#define BATCH  16
#define MLPD   3072
#define NZ     (BATCH*NH)

// ---------------- scratch -----------------------------------------------
__device__ float g_h  [TOKENS*EMB];
__device__ float g_q  [TOKENS*EMB];
__device__ float g_k  [TOKENS*EMB];
__device__ float g_v  [TOKENS*EMB];
__device__ float g_ctx[TOKENS*EMB];
__device__ float g_x1 [TOKENS*EMB];
__device__ float g_h2 [TOKENS*EMB];
__device__ float g_m1 [TOKENS*MLPD];

// ---------------- helpers -----------------------------------------------
__device__ __forceinline__ float gelu_exact(float x) {
    return 0.5f * x * (1.0f + erff(x * 0.70710678118654752440f));
}
__device__ __forceinline__ void cp16(float* dst, const float* src) {
    unsigned int s = (unsigned int)__cvta_generic_to_shared(dst);
    asm volatile("cp.async.cg.shared.global [%0], [%1], 16;\n" :: "r"(s), "l"(src));
}
#define CP_COMMIT()  asm volatile("cp.async.commit_group;\n" ::)
#define CP_WAIT(N)   asm volatile("cp.async.wait_group %0;\n" :: "n"(N))

// ---------------- LayerNorm ----------------------------------------------
__global__ __launch_bounds__(256) void ln_kernel(
    const float* __restrict__ x, const float* __restrict__ g,
    const float* __restrict__ b, float* __restrict__ y)
{
    size_t row = blockIdx.x;
    const float* xr = x + row * EMB;
    int t = threadIdx.x;
    float v0 = xr[t], v1 = xr[t + 256], v2 = xr[t + 512];
    float s  = v0 + v1 + v2;
    float sq = v0*v0 + v1*v1 + v2*v2;
    __shared__ float red0[8], red1[8];
    #pragma unroll
    for (int o = 16; o; o >>= 1) {
        s  += __shfl_xor_sync(0xFFFFFFFFu, s,  o);
        sq += __shfl_xor_sync(0xFFFFFFFFu, sq, o);
    }
    int warp = t >> 5, lane = t & 31;
    if (lane == 0) { red0[warp] = s; red1[warp] = sq; }
    __syncthreads();
    float ts = 0.f, tq = 0.f;
    #pragma unroll
    for (int i = 0; i < 8; i++) { ts += red0[i]; tq += red1[i]; }
    float mu  = ts * (1.0f / EMB);
    float var = tq * (1.0f / EMB) - mu * mu;
    float rs  = rsqrtf(var + 1e-6f);
    float* yr = y + row * EMB;
    yr[t]       = (v0 - mu) * rs * g[t]       + b[t];
    yr[t + 256] = (v1 - mu) * rs * g[t + 256] + b[t + 256];
    yr[t + 512] = (v2 - mu) * rs * g[t + 512] + b[t + 512];
}

// ---------------- pipelined TF32 GEMM, 4 warps, warp tile 64x64 -----------
// EPI: 0 bias, 1 bias+gelu, 2 bias+residual
#define GEMM_SMEM 70656

template<int EPI>
__global__ __launch_bounds__(128, 2) void gemm_tf32_kernel(
    const float* __restrict__ A, const float* __restrict__ B,
    const float* __restrict__ bias, const float* __restrict__ R,
    float* __restrict__ C, int M, int N, int K)
{
    extern __shared__ float sm[];
    float* Asb[2] = { sm,        sm + 4608 };
    float* Bsb[2] = { sm + 9216, sm + 13440 };

    int tid = threadIdx.x;
    int warp = tid >> 5, lane = tid & 31;
    int wr = warp >> 1, wc = warp & 1;          // 2x2 warps, warp tile 64x64
    int rowBase = blockIdx.y * 128;
    int colBase = blockIdx.x * 128;

    wmma::fragment<wmma::accumulator, 16, 16, 8, float> acc[4][4];
    #pragma unroll
    for (int f = 0; f < 4; f++)
        #pragma unroll
        for (int g = 0; g < 4; g++) wmma::fill_fragment(acc[f][g], 0.0f);

    auto load_stage = [&](int buf, int k0) {
        float* As = Asb[buf];
        float* Bs = Bsb[buf];
        #pragma unroll
        for (int i = 0; i < 8; i++) {
            int idx = tid + i * 128;
            int r = idx >> 3, c = (idx & 7) << 2;
            cp16(As + r * 36 + c, A + (size_t)(rowBase + r) * K + k0 + c);
        }
        #pragma unroll
        for (int i = 0; i < 8; i++) {
            int idx = tid + i * 128;
            int r = idx >> 5, c = (idx & 31) << 2;
            cp16(Bs + r * 132 + c, B + (size_t)(k0 + r) * N + colBase + c);
        }
    };

    load_stage(0, 0);
    CP_COMMIT();

    int buf = 0;
    for (int k0 = 0; k0 < K; k0 += 32) {
        if (k0 + 32 < K) {
            load_stage(buf ^ 1, k0 + 32);
            CP_COMMIT();
            CP_WAIT(1);
        } else {
            CP_WAIT(0);
        }
        __syncthreads();
        float* As = Asb[buf];
        float* Bs = Bsb[buf];
        #pragma unroll
        for (int kk = 0; kk < 32; kk += 8) {
            wmma::fragment<wmma::matrix_a, 16, 16, 8, wmma::precision::tf32, wmma::row_major> af[4];
            wmma::fragment<wmma::matrix_b, 16, 16, 8, wmma::precision::tf32, wmma::row_major> bf[4];
            #pragma unroll
            for (int f = 0; f < 4; f++)
                wmma::load_matrix_sync(af[f], As + (wr * 64 + f * 16) * 36 + kk, 36);
            #pragma unroll
            for (int g = 0; g < 4; g++)
                wmma::load_matrix_sync(bf[g], Bs + kk * 132 + wc * 64 + g * 16, 132);
            #pragma unroll
            for (int f = 0; f < 4; f++)
                #pragma unroll
                for (int g = 0; g < 4; g++)
                    wmma::mma_sync(acc[f][g], af[f], bf[g], acc[f][g]);
        }
        __syncthreads();
        buf ^= 1;
    }

    // epilogue via per-warp smem staging
    float* stage = sm + warp * 320;             // [16][20]
    #pragma unroll
    for (int f = 0; f < 4; f++) {
        #pragma unroll
        for (int g = 0; g < 4; g++) {
            wmma::store_matrix_sync(stage, acc[f][g], 20, wmma::mem_row_major);
            __syncwarp();
            int row0 = rowBase + wr * 64 + f * 16;
            int col0 = colBase + wc * 64 + g * 16;
            #pragma unroll
            for (int j = 0; j < 8; j++) {
                int e = lane + j * 32;
                int r = e >> 4, c = e & 15;
                float val = stage[r * 20 + c] + bias[col0 + c];
                if (EPI == 1) val = gelu_exact(val);
                size_t oidx = (size_t)(row0 + r) * N + (col0 + c);
                if (EPI == 2) val += R[oidx];
                C[oidx] = val;
            }
            __syncwarp();
        }
    }
}

// ---------------- flash attention (fused scores+softmax+PV) ---------------
// grid (8, 192), 256 threads. Q tile 128x64 resident; iterate 8 KV tiles of 128.
// smem floats: Qs[128][68] Ks[128][68] Vs[128][68] Ss[128][132] Cs[128][68]
//              mrow[128] lrow[128] arow[128]
#define FLASH_SMEM 208384

__global__ __launch_bounds__(256) void flash_kernel(
    const float* __restrict__ Q, const float* __restrict__ K,
    const float* __restrict__ V, float* __restrict__ Out)
{
    extern __shared__ float fs[];
    float* Qs = fs;             // 8704
    float* Ks = fs + 8704;      // 8704
    float* Vs = fs + 17408;     // 8704
    float* Ss = fs + 26112;     // 16896
    float* Cs = fs + 43008;     // 8704
    float* mrow = fs + 51712;
    float* lrow = mrow + 128;
    float* arow = mrow + 256;

    int z = blockIdx.y, b = z / NH, h = z % NH;
    int rowBase = blockIdx.x * 128;
    const float* Qb = Q + (size_t)b * SLEN * EMB + h * HD;
    const float* Kb = K + (size_t)b * SLEN * EMB + h * HD;
    const float* Vb = V + (size_t)b * SLEN * EMB + h * HD;
    float* Ob = Out + (size_t)b * SLEN * EMB + h * HD;

    int tid = threadIdx.x, warp = tid >> 5, lane = tid & 31;

    // load Q tile; init stats and ctx
    #pragma unroll
    for (int i = 0; i < 8; i++) {
        int idx = tid + i * 256;
        int r = idx >> 4, c = (idx & 15) << 2;
        cp16(Qs + r * 68 + c, Qb + (size_t)(rowBase + r) * EMB + c);
    }
    if (tid < 128) { mrow[tid] = -1e30f; lrow[tid] = 0.0f; }
    #pragma unroll
    for (int i = 0; i < 8; i++) {
        int idx = tid + i * 256;
        int r = idx >> 4, c = (idx & 15) << 2;
        *(float4*)&Cs[r * 68 + c] = make_float4(0.f, 0.f, 0.f, 0.f);
    }
    CP_COMMIT();
    CP_WAIT(0);
    __syncthreads();

    for (int kt = 0; kt < 8; kt++) {
        int kvBase = kt * 128;
        // load K,V tiles
        #pragma unroll
        for (int i = 0; i < 8; i++) {
            int idx = tid + i * 256;
            int r = idx >> 4, c = (idx & 15) << 2;
            cp16(Ks + r * 68 + c, Kb + (size_t)(kvBase + r) * EMB + c);
        }
        #pragma unroll
        for (int i = 0; i < 8; i++) {
            int idx = tid + i * 256;
            int r = idx >> 4, c = (idx & 15) << 2;
            cp16(Vs + r * 68 + c, Vb + (size_t)(kvBase + r) * EMB + c);
        }
        CP_COMMIT();
        CP_WAIT(0);
        __syncthreads();

        // phase 1: S = Q @ K^T / 8  (8 warps as 2x4, warp tile 64x32)
        {
            int wr = warp >> 2, wc = warp & 3;
            wmma::fragment<wmma::accumulator, 16, 16, 8, float> acc[4][2];
            #pragma unroll
            for (int f = 0; f < 4; f++)
                #pragma unroll
                for (int g = 0; g < 2; g++) wmma::fill_fragment(acc[f][g], 0.0f);
            #pragma unroll
            for (int kk = 0; kk < HD; kk += 8) {
                wmma::fragment<wmma::matrix_a, 16, 16, 8, wmma::precision::tf32, wmma::row_major> af[4];
                wmma::fragment<wmma::matrix_b, 16, 16, 8, wmma::precision::tf32, wmma::col_major> bf[2];
                #pragma unroll
                for (int f = 0; f < 4; f++)
                    wmma::load_matrix_sync(af[f], Qs + (wr * 64 + f * 16) * 68 + kk, 68);
                #pragma unroll
                for (int g = 0; g < 2; g++)
                    wmma::load_matrix_sync(bf[g], Ks + (wc * 32 + g * 16) * 68 + kk, 68);
                #pragma unroll
                for (int f = 0; f < 4; f++)
                    #pragma unroll
                    for (int g = 0; g < 2; g++)
                        wmma::mma_sync(acc[f][g], af[f], bf[g], acc[f][g]);
            }
            #pragma unroll
            for (int f = 0; f < 4; f++)
                #pragma unroll
                for (int g = 0; g < 2; g++) {
                    #pragma unroll
                    for (int e = 0; e < acc[f][g].num_elements; e++)
                        acc[f][g].x[e] *= 0.125f;
                    wmma::store_matrix_sync(
                        Ss + (wr * 64 + f * 16) * 132 + wc * 32 + g * 16,
                        acc[f][g], 132, wmma::mem_row_major);
                }
        }
        __syncthreads();

        // phase 2: online softmax (thread pair per row)
        {
            int r = tid >> 1, half = tid & 1;
            float* srow = Ss + r * 132 + half * 64;
            float mx = -1e30f;
            #pragma unroll
            for (int i = 0; i < 16; i++) {
                float4 v = *(float4*)&srow[i * 4];
                mx = fmaxf(mx, fmaxf(fmaxf(v.x, v.y), fmaxf(v.z, v.w)));
            }
            mx = fmaxf(mx, __shfl_xor_sync(0xFFFFFFFFu, mx, 1));
            float mold = mrow[r];
            float mnew = fmaxf(mold, mx);
            float sum = 0.f;
            #pragma unroll
            for (int i = 0; i < 16; i++) {
                float4 v = *(float4*)&srow[i * 4];
                v.x = __expf(v.x - mnew); v.y = __expf(v.y - mnew);
                v.z = __expf(v.z - mnew); v.w = __expf(v.w - mnew);
                sum += v.x + v.y + v.z + v.w;
                *(float4*)&srow[i * 4] = v;
            }
            sum += __shfl_xor_sync(0xFFFFFFFFu, sum, 1);
            if (half == 0) {
                float alpha = __expf(mold - mnew);
                mrow[r] = mnew;
                lrow[r] = lrow[r] * alpha + sum;
                arow[r] = alpha;
            }
        }
        __syncthreads();

        // phase 3: PV = P @ V (8 warps as 4x2, warp tile 32x32)
        {
            int wr = warp >> 1, wc = warp & 1;
            wmma::fragment<wmma::accumulator, 16, 16, 8, float> acc[2][2];
            #pragma unroll
            for (int f = 0; f < 2; f++)
                #pragma unroll
                for (int g = 0; g < 2; g++) wmma::fill_fragment(acc[f][g], 0.0f);
            #pragma unroll
            for (int kk = 0; kk < 128; kk += 8) {
                wmma::fragment<wmma::matrix_a, 16, 16, 8, wmma::precision::tf32, wmma::row_major> af[2];
                wmma::fragment<wmma::matrix_b, 16, 16, 8, wmma::precision::tf32, wmma::row_major> bf[2];
                #pragma unroll
                for (int f = 0; f < 2; f++)
                    wmma::load_matrix_sync(af[f], Ss + (wr * 32 + f * 16) * 132 + kk, 132);
                #pragma unroll
                for (int g = 0; g < 2; g++)
                    wmma::load_matrix_sync(bf[g], Vs + kk * 68 + wc * 32 + g * 16, 68);
                #pragma unroll
                for (int f = 0; f < 2; f++)
                    #pragma unroll
                    for (int g = 0; g < 2; g++)
                        wmma::mma_sync(acc[f][g], af[f], bf[g], acc[f][g]);
            }
            __syncthreads();   // all P reads done before overwriting Ss
            #pragma unroll
            for (int f = 0; f < 2; f++)
                #pragma unroll
                for (int g = 0; g < 2; g++)
                    wmma::store_matrix_sync(
                        Ss + (wr * 32 + f * 16) * 132 + wc * 32 + g * 16,
                        acc[f][g], 132, wmma::mem_row_major);
        }
        __syncthreads();

        // phase 4: ctx = ctx * alpha + PV
        #pragma unroll
        for (int i = 0; i < 8; i++) {
            int idx = tid + i * 256;
            int r = idx >> 4, c = (idx & 15) << 2;
            float a = arow[r];
            float4 cv = *(float4*)&Cs[r * 68 + c];
            float4 pv = *(float4*)&Ss[r * 132 + c];
            cv.x = cv.x * a + pv.x; cv.y = cv.y * a + pv.y;
            cv.z = cv.z * a + pv.z; cv.w = cv.w * a + pv.w;
            *(float4*)&Cs[r * 68 + c] = cv;
        }
        __syncthreads();
    }

    // epilogue: out = ctx / l
    #pragma unroll
    for (int i = 0; i < 8; i++) {
        int idx = tid + i * 256;
        int r = idx >> 4, c = (idx & 15) << 2;
        float inv = 1.0f / lrow[r];
        float4 cv = *(float4*)&Cs[r * 68 + c];
        cv.x *= inv; cv.y *= inv; cv.z *= inv; cv.w *= inv;
        *(float4*)(Ob + (size_t)(rowBase + r) * EMB + c) = cv;
    }
}

// ---------------- launch --------------------------------------------------
extern "C" void kernel_launch(void* const* d_in, const int* in_sizes, int n_in,
                              void* d_out, int out_size)
{
    const float* x     = (const float*)d_in[0];
    const float* ln1_g = (const float*)d_in[1];
    const float* ln1_b = (const float*)d_in[2];
    const float* Wq    = (const float*)d_in[3];
    const float* bq    = (const float*)d_in[4];
    const float* Wk    = (const float*)d_in[5];
    const float* bk    = (const float*)d_in[6];
    const float* Wv    = (const float*)d_in[7];
    const float* bv    = (const float*)d_in[8];
    const float* Wo    = (const float*)d_in[9];
    const float* bo    = (const float*)d_in[10];
    const float* ln2_g = (const float*)d_in[11];
    const float* ln2_b = (const float*)d_in[12];
    const float* W1    = (const float*)d_in[13];
    const float* b1    = (const float*)d_in[14];
    const float* W2    = (const float*)d_in[15];
    const float* b2    = (const float*)d_in[16];
    float* out = (float*)d_out;

    float *p_h, *p_q, *p_k, *p_v, *p_ctx, *p_x1, *p_h2, *p_m1;
    cudaGetSymbolAddress((void**)&p_h,   g_h);
    cudaGetSymbolAddress((void**)&p_q,   g_q);
    cudaGetSymbolAddress((void**)&p_k,   g_k);
    cudaGetSymbolAddress((void**)&p_v,   g_v);
    cudaGetSymbolAddress((void**)&p_ctx, g_ctx);
    cudaGetSymbolAddress((void**)&p_x1,  g_x1);
    cudaGetSymbolAddress((void**)&p_h2,  g_h2);
    cudaGetSymbolAddress((void**)&p_m1,  g_m1);

    cudaFuncSetAttribute(gemm_tf32_kernel<0>, cudaFuncAttributeMaxDynamicSharedMemorySize, GEMM_SMEM);
    cudaFuncSetAttribute(gemm_tf32_kernel<1>, cudaFuncAttributeMaxDynamicSharedMemorySize, GEMM_SMEM);
    cudaFuncSetAttribute(gemm_tf32_kernel<2>, cudaFuncAttributeMaxDynamicSharedMemorySize, GEMM_SMEM);
    cudaFuncSetAttribute(flash_kernel,        cudaFuncAttributeMaxDynamicSharedMemorySize, FLASH_SMEM);

    dim3 gProj(EMB / 128, TOKENS / 128);    // (6, 128)
    dim3 gMlp1(MLPD / 128, TOKENS / 128);   // (24, 128)

    ln_kernel<<<TOKENS, 256>>>(x, ln1_g, ln1_b, p_h);
    gemm_tf32_kernel<0><<<gProj, 128, GEMM_SMEM>>>(p_h, Wq, bq, nullptr, p_q, TOKENS, EMB, EMB);
    gemm_tf32_kernel<0><<<gProj, 128, GEMM_SMEM>>>(p_h, Wk, bk, nullptr, p_k, TOKENS, EMB, EMB);
    gemm_tf32_kernel<0><<<gProj, 128, GEMM_SMEM>>>(p_h, Wv, bv, nullptr, p_v, TOKENS, EMB, EMB);
    flash_kernel<<<dim3(SLEN / 128, NZ), 256, FLASH_SMEM>>>(p_q, p_k, p_v, p_ctx);
    gemm_tf32_kernel<2><<<gProj, 128, GEMM_SMEM>>>(p_ctx, Wo, bo, x, p_x1, TOKENS, EMB, EMB);
    ln_kernel<<<TOKENS, 256>>>(p_x1, ln2_g, ln2_b, p_h2);
    gemm_tf32_kernel<1><<<gMlp1, 128, GEMM_SMEM>>>(p_h2, W1, b1, nullptr, p_m1, TOKENS, MLPD, EMB);
    gemm_tf32_kernel<2><<<gProj, 128, GEMM_SMEM>>>(p_m1, W2, b2, p_x1, out, TOKENS, EMB, MLPD);
}

// round 7
// speedup vs baseline: 3.5707x; 2.7041x over previous
#include <cuda_runtime.h>
#include <cuda_fp16.h>
#include <cstdint>
#include <mma.h>
#include <math.h>

using namespace nvcuda;

#define TOKENS 16384
#define EMB    768
#define NH     12
#define HD     64
#define SLEN   1024
#define BATCH  16
#define MLPD   3072
#define NZ     (BATCH*NH)

// ---------------- scratch -----------------------------------------------
__device__ __half hW_q[EMB*EMB];
__device__ __half hW_k[EMB*EMB];
__device__ __half hW_v[EMB*EMB];
__device__ __half hW_o[EMB*EMB];
__device__ __half hW_1[EMB*MLPD];
__device__ __half hW_2[MLPD*EMB];
__device__ __half g_h  [TOKENS*EMB];
__device__ __half g_q  [TOKENS*EMB];
__device__ __half g_k  [TOKENS*EMB];
__device__ __half g_v  [TOKENS*EMB];
__device__ __half g_ctx[TOKENS*EMB];
__device__ __half g_h2 [TOKENS*EMB];
__device__ __half g_m1 [TOKENS*MLPD];
__device__ float  g_x1 [TOKENS*EMB];

// ---------------- helpers -----------------------------------------------
__device__ __forceinline__ float gelu_exact(float x) {
    return 0.5f * x * (1.0f + erff(x * 0.70710678118654752440f));
}
__device__ __forceinline__ void cp16(void* dst, const void* src) {
    unsigned int s = (unsigned int)__cvta_generic_to_shared(dst);
    asm volatile("cp.async.cg.shared.global [%0], [%1], 16;\n" :: "r"(s), "l"(src));
}
#define CP_COMMIT()  asm volatile("cp.async.commit_group;\n" ::)
#define CP_WAIT(N)   asm volatile("cp.async.wait_group %0;\n" :: "n"(N))

// ---------------- fp32 -> fp16 convert ------------------------------------
__global__ __launch_bounds__(256) void f2h_kernel(
    const float* __restrict__ in, __half* __restrict__ out, int n)
{
    int i = (blockIdx.x * blockDim.x + threadIdx.x) * 4;
    if (i < n) {
        float4 v = *(const float4*)(in + i);
        *(__half2*)(out + i)     = __floats2half2_rn(v.x, v.y);
        *(__half2*)(out + i + 2) = __floats2half2_rn(v.z, v.w);
    }
}

// ---------------- LayerNorm (fp32 in, fp16 out) ---------------------------
__global__ __launch_bounds__(256) void ln_kernel(
    const float* __restrict__ x, const float* __restrict__ g,
    const float* __restrict__ b, __half* __restrict__ y)
{
    size_t row = blockIdx.x;
    const float* xr = x + row * EMB;
    int t = threadIdx.x;
    float v0 = xr[t], v1 = xr[t + 256], v2 = xr[t + 512];
    float s  = v0 + v1 + v2;
    float sq = v0*v0 + v1*v1 + v2*v2;
    __shared__ float red0[8], red1[8];
    #pragma unroll
    for (int o = 16; o; o >>= 1) {
        s  += __shfl_xor_sync(0xFFFFFFFFu, s,  o);
        sq += __shfl_xor_sync(0xFFFFFFFFu, sq, o);
    }
    int warp = t >> 5, lane = t & 31;
    if (lane == 0) { red0[warp] = s; red1[warp] = sq; }
    __syncthreads();
    float ts = 0.f, tq = 0.f;
    #pragma unroll
    for (int i = 0; i < 8; i++) { ts += red0[i]; tq += red1[i]; }
    float mu  = ts * (1.0f / EMB);
    float var = tq * (1.0f / EMB) - mu * mu;
    float rs  = rsqrtf(var + 1e-6f);
    __half* yr = y + row * EMB;
    yr[t]       = __float2half((v0 - mu) * rs * g[t]       + b[t]);
    yr[t + 256] = __float2half((v1 - mu) * rs * g[t + 256] + b[t + 256]);
    yr[t + 512] = __float2half((v2 - mu) * rs * g[t + 512] + b[t + 512]);
}

// ---------------- pipelined FP16 GEMM, 4 warps, warp tile 64x64 -----------
// EPI: 0 bias (half out), 1 bias+gelu (half out), 2 bias+residual (float out)
// smem (halves): As[2] 128x40 (5120 each), Bs[2] 32x136 (4352 each) = 37888 B
#define GEMM_SMEM 37888

template<int EPI>
__global__ __launch_bounds__(128, 2) void gemm_fp16_kernel(
    const __half* __restrict__ A, const __half* __restrict__ B,
    const float* __restrict__ bias, const float* __restrict__ R,
    void* __restrict__ Cv, int M, int N, int K)
{
    extern __shared__ __half smh[];
    __half* Asb[2] = { smh,         smh + 5120 };
    __half* Bsb[2] = { smh + 10240, smh + 14592 };

    int tid = threadIdx.x;
    int warp = tid >> 5, lane = tid & 31;
    int wr = warp >> 1, wc = warp & 1;          // 2x2 warps, warp tile 64x64
    int rowBase = blockIdx.y * 128;
    int colBase = blockIdx.x * 128;

    wmma::fragment<wmma::accumulator, 16, 16, 16, float> acc[4][4];
    #pragma unroll
    for (int f = 0; f < 4; f++)
        #pragma unroll
        for (int g = 0; g < 4; g++) wmma::fill_fragment(acc[f][g], 0.0f);

    auto load_stage = [&](int buf, int k0) {
        __half* As = Asb[buf];
        __half* Bs = Bsb[buf];
        #pragma unroll
        for (int i = 0; i < 4; i++) {           // 512 chunks of 8 halves
            int idx = tid + i * 128;
            int r = idx >> 2, ch = idx & 3;
            cp16(As + r * 40 + ch * 8, A + (size_t)(rowBase + r) * K + k0 + ch * 8);
        }
        #pragma unroll
        for (int i = 0; i < 4; i++) {           // 512 chunks
            int idx = tid + i * 128;
            int r = idx >> 4, ch = idx & 15;
            cp16(Bs + r * 136 + ch * 8, B + (size_t)(k0 + r) * N + colBase + ch * 8);
        }
    };

    load_stage(0, 0);
    CP_COMMIT();

    int buf = 0;
    for (int k0 = 0; k0 < K; k0 += 32) {
        if (k0 + 32 < K) {
            load_stage(buf ^ 1, k0 + 32);
            CP_COMMIT();
            CP_WAIT(1);
        } else {
            CP_WAIT(0);
        }
        __syncthreads();
        __half* As = Asb[buf];
        __half* Bs = Bsb[buf];
        #pragma unroll
        for (int kk = 0; kk < 32; kk += 16) {
            wmma::fragment<wmma::matrix_a, 16, 16, 16, __half, wmma::row_major> af[4];
            wmma::fragment<wmma::matrix_b, 16, 16, 16, __half, wmma::row_major> bf[4];
            #pragma unroll
            for (int f = 0; f < 4; f++)
                wmma::load_matrix_sync(af[f], As + (wr * 64 + f * 16) * 40 + kk, 40);
            #pragma unroll
            for (int g = 0; g < 4; g++)
                wmma::load_matrix_sync(bf[g], Bs + kk * 136 + wc * 64 + g * 16, 136);
            #pragma unroll
            for (int f = 0; f < 4; f++)
                #pragma unroll
                for (int g = 0; g < 4; g++)
                    wmma::mma_sync(acc[f][g], af[f], bf[g], acc[f][g]);
        }
        __syncthreads();
        buf ^= 1;
    }

    // epilogue via per-warp smem staging (reuse smem as float)
    float* stage = (float*)smh + warp * 320;    // [16][20]
    #pragma unroll
    for (int f = 0; f < 4; f++) {
        #pragma unroll
        for (int g = 0; g < 4; g++) {
            wmma::store_matrix_sync(stage, acc[f][g], 20, wmma::mem_row_major);
            __syncwarp();
            int row0 = rowBase + wr * 64 + f * 16;
            int col0 = colBase + wc * 64 + g * 16;
            #pragma unroll
            for (int j = 0; j < 8; j++) {
                int e = lane + j * 32;
                int r = e >> 4, c = e & 15;
                float val = stage[r * 20 + c] + bias[col0 + c];
                if (EPI == 1) val = gelu_exact(val);
                size_t oidx = (size_t)(row0 + r) * N + (col0 + c);
                if (EPI == 2) {
                    ((float*)Cv)[oidx] = val + R[oidx];
                } else {
                    ((__half*)Cv)[oidx] = __float2half(val);
                }
            }
            __syncwarp();
        }
    }
}

// ---------------- flash attention (fp16 in/out, fp32 softmax) -------------
// grid (8, 192), 256 threads. smem 194048 B.
#define FLASH_SMEM 194048

__global__ __launch_bounds__(256) void flash_kernel(
    const __half* __restrict__ Q, const __half* __restrict__ K,
    const __half* __restrict__ V, __half* __restrict__ Out)
{
    extern __shared__ char fsm[];
    __half* Qs = (__half*)fsm;                 // 128x72 = 18432 B
    __half* Ks = (__half*)(fsm + 18432);
    __half* Vs = (__half*)(fsm + 36864);
    float*  Ss = (float*)(fsm + 55296);        // 128x132 f32 = 67584 B
    __half* Ps = (__half*)(fsm + 122880);      // 128x136 f16 = 34816 B
    float*  Cs = (float*)(fsm + 157696);       // 128x68 f32 = 34816 B
    float*  mrow = (float*)(fsm + 192512);
    float*  lrow = mrow + 128;
    float*  arow = mrow + 256;

    int z = blockIdx.y, b = z / NH, h = z % NH;
    int rowBase = blockIdx.x * 128;
    const __half* Qb = Q + (size_t)b * SLEN * EMB + h * HD;
    const __half* Kb = K + (size_t)b * SLEN * EMB + h * HD;
    const __half* Vb = V + (size_t)b * SLEN * EMB + h * HD;
    __half* Ob = Out + (size_t)b * SLEN * EMB + h * HD;

    int tid = threadIdx.x, warp = tid >> 5;

    // load Q tile; init stats and ctx
    #pragma unroll
    for (int i = 0; i < 4; i++) {              // 1024 chunks of 8 halves
        int idx = tid + i * 256;
        int r = idx >> 3, ch = idx & 7;
        cp16(Qs + r * 72 + ch * 8, Qb + (size_t)(rowBase + r) * EMB + ch * 8);
    }
    if (tid < 128) { mrow[tid] = -1e30f; lrow[tid] = 0.0f; }
    #pragma unroll
    for (int i = 0; i < 8; i++) {
        int idx = tid + i * 256;
        int r = idx >> 4, c = (idx & 15) << 2;
        *(float4*)&Cs[r * 68 + c] = make_float4(0.f, 0.f, 0.f, 0.f);
    }
    CP_COMMIT();
    CP_WAIT(0);
    __syncthreads();

    for (int kt = 0; kt < 8; kt++) {
        int kvBase = kt * 128;
        #pragma unroll
        for (int i = 0; i < 4; i++) {
            int idx = tid + i * 256;
            int r = idx >> 3, ch = idx & 7;
            cp16(Ks + r * 72 + ch * 8, Kb + (size_t)(kvBase + r) * EMB + ch * 8);
        }
        #pragma unroll
        for (int i = 0; i < 4; i++) {
            int idx = tid + i * 256;
            int r = idx >> 3, ch = idx & 7;
            cp16(Vs + r * 72 + ch * 8, Vb + (size_t)(kvBase + r) * EMB + ch * 8);
        }
        CP_COMMIT();
        CP_WAIT(0);
        __syncthreads();

        // phase 1: S = Q @ K^T / 8  (2x4 warps, warp tile 64x32)
        {
            int wr = warp >> 2, wc = warp & 3;
            wmma::fragment<wmma::accumulator, 16, 16, 16, float> acc[4][2];
            #pragma unroll
            for (int f = 0; f < 4; f++)
                #pragma unroll
                for (int g = 0; g < 2; g++) wmma::fill_fragment(acc[f][g], 0.0f);
            #pragma unroll
            for (int kk = 0; kk < HD; kk += 16) {
                wmma::fragment<wmma::matrix_a, 16, 16, 16, __half, wmma::row_major> af[4];
                wmma::fragment<wmma::matrix_b, 16, 16, 16, __half, wmma::col_major> bf[2];
                #pragma unroll
                for (int f = 0; f < 4; f++)
                    wmma::load_matrix_sync(af[f], Qs + (wr * 64 + f * 16) * 72 + kk, 72);
                #pragma unroll
                for (int g = 0; g < 2; g++)
                    wmma::load_matrix_sync(bf[g], Ks + (wc * 32 + g * 16) * 72 + kk, 72);
                #pragma unroll
                for (int f = 0; f < 4; f++)
                    #pragma unroll
                    for (int g = 0; g < 2; g++)
                        wmma::mma_sync(acc[f][g], af[f], bf[g], acc[f][g]);
            }
            #pragma unroll
            for (int f = 0; f < 4; f++)
                #pragma unroll
                for (int g = 0; g < 2; g++) {
                    #pragma unroll
                    for (int e = 0; e < acc[f][g].num_elements; e++)
                        acc[f][g].x[e] *= 0.125f;
                    wmma::store_matrix_sync(
                        Ss + (wr * 64 + f * 16) * 132 + wc * 32 + g * 16,
                        acc[f][g], 132, wmma::mem_row_major);
                }
        }
        __syncthreads();

        // phase 2: online softmax; P -> fp16 Ps
        {
            int r = tid >> 1, half = tid & 1;
            float*  srow = Ss + r * 132 + half * 64;
            __half* prow = Ps + r * 136 + half * 64;
            float mx = -1e30f;
            #pragma unroll
            for (int i = 0; i < 16; i++) {
                float4 v = *(float4*)&srow[i * 4];
                mx = fmaxf(mx, fmaxf(fmaxf(v.x, v.y), fmaxf(v.z, v.w)));
            }
            mx = fmaxf(mx, __shfl_xor_sync(0xFFFFFFFFu, mx, 1));
            float mold = mrow[r];
            float mnew = fmaxf(mold, mx);
            float sum = 0.f;
            #pragma unroll
            for (int i = 0; i < 16; i++) {
                float4 v = *(float4*)&srow[i * 4];
                v.x = __expf(v.x - mnew); v.y = __expf(v.y - mnew);
                v.z = __expf(v.z - mnew); v.w = __expf(v.w - mnew);
                sum += v.x + v.y + v.z + v.w;
                *(__half2*)&prow[i * 4]     = __floats2half2_rn(v.x, v.y);
                *(__half2*)&prow[i * 4 + 2] = __floats2half2_rn(v.z, v.w);
            }
            sum += __shfl_xor_sync(0xFFFFFFFFu, sum, 1);
            if (half == 0) {
                float alpha = __expf(mold - mnew);
                mrow[r] = mnew;
                lrow[r] = lrow[r] * alpha + sum;
                arow[r] = alpha;
            }
        }
        __syncthreads();

        // phase 3: PV = P @ V (4x2 warps, warp tile 32x32); writes Ss
        {
            int wr = warp >> 1, wc = warp & 1;
            wmma::fragment<wmma::accumulator, 16, 16, 16, float> acc[2][2];
            #pragma unroll
            for (int f = 0; f < 2; f++)
                #pragma unroll
                for (int g = 0; g < 2; g++) wmma::fill_fragment(acc[f][g], 0.0f);
            #pragma unroll
            for (int kk = 0; kk < 128; kk += 16) {
                wmma::fragment<wmma::matrix_a, 16, 16, 16, __half, wmma::row_major> af[2];
                wmma::fragment<wmma::matrix_b, 16, 16, 16, __half, wmma::row_major> bf[2];
                #pragma unroll
                for (int f = 0; f < 2; f++)
                    wmma::load_matrix_sync(af[f], Ps + (wr * 32 + f * 16) * 136 + kk, 136);
                #pragma unroll
                for (int g = 0; g < 2; g++)
                    wmma::load_matrix_sync(bf[g], Vs + kk * 72 + wc * 32 + g * 16, 72);
                #pragma unroll
                for (int f = 0; f < 2; f++)
                    #pragma unroll
                    for (int g = 0; g < 2; g++)
                        wmma::mma_sync(acc[f][g], af[f], bf[g], acc[f][g]);
            }
            #pragma unroll
            for (int f = 0; f < 2; f++)
                #pragma unroll
                for (int g = 0; g < 2; g++)
                    wmma::store_matrix_sync(
                        Ss + (wr * 32 + f * 16) * 132 + wc * 32 + g * 16,
                        acc[f][g], 132, wmma::mem_row_major);
        }
        __syncthreads();

        // phase 4: ctx = ctx * alpha + PV
        #pragma unroll
        for (int i = 0; i < 8; i++) {
            int idx = tid + i * 256;
            int r = idx >> 4, c = (idx & 15) << 2;
            float a = arow[r];
            float4 cv = *(float4*)&Cs[r * 68 + c];
            float4 pv = *(float4*)&Ss[r * 132 + c];
            cv.x = cv.x * a + pv.x; cv.y = cv.y * a + pv.y;
            cv.z = cv.z * a + pv.z; cv.w = cv.w * a + pv.w;
            *(float4*)&Cs[r * 68 + c] = cv;
        }
        __syncthreads();
    }

    // epilogue: out = ctx / l (fp16)
    #pragma unroll
    for (int i = 0; i < 8; i++) {
        int idx = tid + i * 256;
        int r = idx >> 4, c = (idx & 15) << 2;
        float inv = 1.0f / lrow[r];
        float4 cv = *(float4*)&Cs[r * 68 + c];
        __half* op = Ob + (size_t)(rowBase + r) * EMB + c;
        *(__half2*)op       = __floats2half2_rn(cv.x * inv, cv.y * inv);
        *(__half2*)(op + 2) = __floats2half2_rn(cv.z * inv, cv.w * inv);
    }
}

// ---------------- launch --------------------------------------------------
extern "C" void kernel_launch(void* const* d_in, const int* in_sizes, int n_in,
                              void* d_out, int out_size)
{
    const float* x     = (const float*)d_in[0];
    const float* ln1_g = (const float*)d_in[1];
    const float* ln1_b = (const float*)d_in[2];
    const float* Wq    = (const float*)d_in[3];
    const float* bq    = (const float*)d_in[4];
    const float* Wk    = (const float*)d_in[5];
    const float* bk    = (const float*)d_in[6];
    const float* Wv    = (const float*)d_in[7];
    const float* bv    = (const float*)d_in[8];
    const float* Wo    = (const float*)d_in[9];
    const float* bo    = (const float*)d_in[10];
    const float* ln2_g = (const float*)d_in[11];
    const float* ln2_b = (const float*)d_in[12];
    const float* W1    = (const float*)d_in[13];
    const float* b1    = (const float*)d_in[14];
    const float* W2    = (const float*)d_in[15];
    const float* b2    = (const float*)d_in[16];
    float* out = (float*)d_out;

    __half *pWq, *pWk, *pWv, *pWo, *pW1, *pW2;
    __half *p_h, *p_q, *p_k, *p_v, *p_ctx, *p_h2, *p_m1;
    float  *p_x1;
    cudaGetSymbolAddress((void**)&pWq,  hW_q);
    cudaGetSymbolAddress((void**)&pWk,  hW_k);
    cudaGetSymbolAddress((void**)&pWv,  hW_v);
    cudaGetSymbolAddress((void**)&pWo,  hW_o);
    cudaGetSymbolAddress((void**)&pW1,  hW_1);
    cudaGetSymbolAddress((void**)&pW2,  hW_2);
    cudaGetSymbolAddress((void**)&p_h,   g_h);
    cudaGetSymbolAddress((void**)&p_q,   g_q);
    cudaGetSymbolAddress((void**)&p_k,   g_k);
    cudaGetSymbolAddress((void**)&p_v,   g_v);
    cudaGetSymbolAddress((void**)&p_ctx, g_ctx);
    cudaGetSymbolAddress((void**)&p_h2,  g_h2);
    cudaGetSymbolAddress((void**)&p_m1,  g_m1);
    cudaGetSymbolAddress((void**)&p_x1,  g_x1);

    cudaFuncSetAttribute(gemm_fp16_kernel<0>, cudaFuncAttributeMaxDynamicSharedMemorySize, GEMM_SMEM);
    cudaFuncSetAttribute(gemm_fp16_kernel<1>, cudaFuncAttributeMaxDynamicSharedMemorySize, GEMM_SMEM);
    cudaFuncSetAttribute(gemm_fp16_kernel<2>, cudaFuncAttributeMaxDynamicSharedMemorySize, GEMM_SMEM);
    cudaFuncSetAttribute(flash_kernel,        cudaFuncAttributeMaxDynamicSharedMemorySize, FLASH_SMEM);

    // weight conversion
    const int CT = 256;
    f2h_kernel<<<(EMB*EMB/4 + CT-1)/CT, CT>>>(Wq, pWq, EMB*EMB);
    f2h_kernel<<<(EMB*EMB/4 + CT-1)/CT, CT>>>(Wk, pWk, EMB*EMB);
    f2h_kernel<<<(EMB*EMB/4 + CT-1)/CT, CT>>>(Wv, pWv, EMB*EMB);
    f2h_kernel<<<(EMB*EMB/4 + CT-1)/CT, CT>>>(Wo, pWo, EMB*EMB);
    f2h_kernel<<<(EMB*MLPD/4 + CT-1)/CT, CT>>>(W1, pW1, EMB*MLPD);
    f2h_kernel<<<(MLPD*EMB/4 + CT-1)/CT, CT>>>(W2, pW2, MLPD*EMB);

    dim3 gProj(EMB / 128, TOKENS / 128);    // (6, 128)
    dim3 gMlp1(MLPD / 128, TOKENS / 128);   // (24, 128)

    ln_kernel<<<TOKENS, 256>>>(x, ln1_g, ln1_b, p_h);
    gemm_fp16_kernel<0><<<gProj, 128, GEMM_SMEM>>>(p_h, pWq, bq, nullptr, p_q, TOKENS, EMB, EMB);
    gemm_fp16_kernel<0><<<gProj, 128, GEMM_SMEM>>>(p_h, pWk, bk, nullptr, p_k, TOKENS, EMB, EMB);
    gemm_fp16_kernel<0><<<gProj, 128, GEMM_SMEM>>>(p_h, pWv, bv, nullptr, p_v, TOKENS, EMB, EMB);
    flash_kernel<<<dim3(SLEN / 128, NZ), 256, FLASH_SMEM>>>(p_q, p_k, p_v, p_ctx);
    gemm_fp16_kernel<2><<<gProj, 128, GEMM_SMEM>>>(p_ctx, pWo, bo, x, p_x1, TOKENS, EMB, EMB);
    ln_kernel<<<TOKENS, 256>>>(p_x1, ln2_g, ln2_b, p_h2);
    gemm_fp16_kernel<1><<<gMlp1, 128, GEMM_SMEM>>>(p_h2, pW1, b1, nullptr, p_m1, TOKENS, MLPD, EMB);
    gemm_fp16_kernel<2><<<gProj, 128, GEMM_SMEM>>>(p_m1, pW2, b2, p_x1, out, TOKENS, EMB, MLPD);
}

// round 8
// speedup vs baseline: 3.8579x; 1.0805x over previous
#include <cuda_runtime.h>
#include <cuda_fp16.h>
#include <cstdint>
#include <mma.h>
#include <math.h>

using namespace nvcuda;

#define TOKENS 16384
#define EMB    768
#define NH     12
#define HD     64
#define SLEN   1024
#define BATCH  16
#define MLPD   3072
#define NZ     (BATCH*NH)
#define QKVN   2304

// ---------------- scratch -----------------------------------------------
__device__ __half hW_qkv[EMB*QKVN];
__device__ __half hW_o[EMB*EMB];
__device__ __half hW_1[EMB*MLPD];
__device__ __half hW_2[MLPD*EMB];
__device__ float  g_bqkv[QKVN];
__device__ __half g_h  [TOKENS*EMB];
__device__ __half g_qkv[(size_t)TOKENS*QKVN];
__device__ __half g_ctx[TOKENS*EMB];
__device__ __half g_h2 [TOKENS*EMB];
__device__ __half g_m1 [TOKENS*MLPD];
__device__ float  g_x1 [TOKENS*EMB];

// ---------------- helpers -----------------------------------------------
__device__ __forceinline__ float gelu_exact(float x) {
    return 0.5f * x * (1.0f + erff(x * 0.70710678118654752440f));
}
__device__ __forceinline__ void cp16(void* dst, const void* src) {
    unsigned int s = (unsigned int)__cvta_generic_to_shared(dst);
    asm volatile("cp.async.cg.shared.global [%0], [%1], 16;\n" :: "r"(s), "l"(src));
}
#define CP_COMMIT()  asm volatile("cp.async.commit_group;\n" ::)
#define CP_WAIT(N)   asm volatile("cp.async.wait_group %0;\n" :: "n"(N))

// ---------------- converts / packing --------------------------------------
__global__ __launch_bounds__(256) void f2h_kernel(
    const float* __restrict__ in, __half* __restrict__ out, int n)
{
    int i = (blockIdx.x * blockDim.x + threadIdx.x) * 4;
    if (i < n) {
        float4 v = *(const float4*)(in + i);
        *(__half2*)(out + i)     = __floats2half2_rn(v.x, v.y);
        *(__half2*)(out + i + 2) = __floats2half2_rn(v.z, v.w);
    }
}
// W [768,768] fp32 -> out [768,2304] fp16 at column block `which`
__global__ __launch_bounds__(256) void packW_kernel(
    const float* __restrict__ W, __half* __restrict__ out, int which)
{
    int i = (blockIdx.x * blockDim.x + threadIdx.x) * 4;
    if (i < EMB * EMB) {
        float4 v = *(const float4*)(W + i);
        int r = i / EMB, c = i % EMB;
        __half* o = out + (size_t)r * QKVN + which * EMB + c;
        *(__half2*)o       = __floats2half2_rn(v.x, v.y);
        *(__half2*)(o + 2) = __floats2half2_rn(v.z, v.w);
    }
}
__global__ __launch_bounds__(256) void packb_kernel(
    const float* __restrict__ b0, const float* __restrict__ b1,
    const float* __restrict__ b2, float* __restrict__ out)
{
    int i = blockIdx.x * blockDim.x + threadIdx.x;
    if (i < QKVN) {
        int which = i / EMB, j = i % EMB;
        out[i] = which == 0 ? b0[j] : (which == 1 ? b1[j] : b2[j]);
    }
}

// ---------------- LayerNorm (fp32 in, fp16 out) ---------------------------
__global__ __launch_bounds__(256) void ln_kernel(
    const float* __restrict__ x, const float* __restrict__ g,
    const float* __restrict__ b, __half* __restrict__ y)
{
    size_t row = blockIdx.x;
    const float* xr = x + row * EMB;
    int t = threadIdx.x;
    float v0 = xr[t], v1 = xr[t + 256], v2 = xr[t + 512];
    float s  = v0 + v1 + v2;
    float sq = v0*v0 + v1*v1 + v2*v2;
    __shared__ float red0[8], red1[8];
    #pragma unroll
    for (int o = 16; o; o >>= 1) {
        s  += __shfl_xor_sync(0xFFFFFFFFu, s,  o);
        sq += __shfl_xor_sync(0xFFFFFFFFu, sq, o);
    }
    int warp = t >> 5, lane = t & 31;
    if (lane == 0) { red0[warp] = s; red1[warp] = sq; }
    __syncthreads();
    float ts = 0.f, tq = 0.f;
    #pragma unroll
    for (int i = 0; i < 8; i++) { ts += red0[i]; tq += red1[i]; }
    float mu  = ts * (1.0f / EMB);
    float var = tq * (1.0f / EMB) - mu * mu;
    float rs  = rsqrtf(var + 1e-6f);
    __half* yr = y + row * EMB;
    yr[t]       = __float2half((v0 - mu) * rs * g[t]       + b[t]);
    yr[t + 256] = __float2half((v1 - mu) * rs * g[t + 256] + b[t + 256]);
    yr[t + 512] = __float2half((v2 - mu) * rs * g[t + 512] + b[t + 512]);
}

// ---------------- 3-stage pipelined FP16 GEMM, warp tile 64x64 ------------
// EPI: 0 bias (half out), 1 bias+gelu (half out), 2 bias+residual (float out)
// stage: As 128x40 halves + Bs 32x136 halves = 9472 halves = 18944 B; x3
#define GEMM_SMEM 56832

template<int EPI>
__global__ __launch_bounds__(128, 2) void gemm_fp16_kernel(
    const __half* __restrict__ A, const __half* __restrict__ B,
    const float* __restrict__ bias, const float* __restrict__ R,
    void* __restrict__ Cv, int M, int N, int K)
{
    extern __shared__ __half smh[];
    int tid = threadIdx.x;
    int warp = tid >> 5, lane = tid & 31;
    int wr = warp >> 1, wc = warp & 1;
    int rowBase = blockIdx.y * 128;
    int colBase = blockIdx.x * 128;

    wmma::fragment<wmma::accumulator, 16, 16, 16, float> acc[4][4];
    #pragma unroll
    for (int f = 0; f < 4; f++)
        #pragma unroll
        for (int g = 0; g < 4; g++) wmma::fill_fragment(acc[f][g], 0.0f);

    auto load_stage = [&](int s, int k0) {
        __half* As = smh + s * 9472;
        __half* Bs = As + 5120;
        #pragma unroll
        for (int i = 0; i < 4; i++) {
            int idx = tid + i * 128;
            int r = idx >> 2, ch = idx & 3;
            cp16(As + r * 40 + ch * 8, A + (size_t)(rowBase + r) * K + k0 + ch * 8);
        }
        #pragma unroll
        for (int i = 0; i < 4; i++) {
            int idx = tid + i * 128;
            int r = idx >> 4, ch = idx & 15;
            cp16(Bs + r * 136 + ch * 8, B + (size_t)(k0 + r) * N + colBase + ch * 8);
        }
    };

    const int NS = K / 32;
    load_stage(0, 0);
    CP_COMMIT();
    load_stage(1, 32);
    CP_COMMIT();

    for (int i = 0; i < NS; i++) {
        if (i + 1 < NS) { CP_WAIT(1); } else { CP_WAIT(0); }
        __syncthreads();
        if (i + 2 < NS) {
            load_stage((i + 2) % 3, (i + 2) * 32);
            CP_COMMIT();
        }
        __half* As = smh + (i % 3) * 9472;
        __half* Bs = As + 5120;
        #pragma unroll
        for (int kk = 0; kk < 32; kk += 16) {
            wmma::fragment<wmma::matrix_a, 16, 16, 16, __half, wmma::row_major> af[4];
            wmma::fragment<wmma::matrix_b, 16, 16, 16, __half, wmma::row_major> bf[4];
            #pragma unroll
            for (int f = 0; f < 4; f++)
                wmma::load_matrix_sync(af[f], As + (wr * 64 + f * 16) * 40 + kk, 40);
            #pragma unroll
            for (int g = 0; g < 4; g++)
                wmma::load_matrix_sync(bf[g], Bs + kk * 136 + wc * 64 + g * 16, 136);
            #pragma unroll
            for (int f = 0; f < 4; f++)
                #pragma unroll
                for (int g = 0; g < 4; g++)
                    wmma::mma_sync(acc[f][g], af[f], bf[g], acc[f][g]);
        }
    }
    __syncthreads();

    float* stage = (float*)smh + warp * 320;
    #pragma unroll
    for (int f = 0; f < 4; f++) {
        #pragma unroll
        for (int g = 0; g < 4; g++) {
            wmma::store_matrix_sync(stage, acc[f][g], 20, wmma::mem_row_major);
            __syncwarp();
            int row0 = rowBase + wr * 64 + f * 16;
            int col0 = colBase + wc * 64 + g * 16;
            #pragma unroll
            for (int j = 0; j < 8; j++) {
                int e = lane + j * 32;
                int r = e >> 4, c = e & 15;
                float val = stage[r * 20 + c] + bias[col0 + c];
                if (EPI == 1) val = gelu_exact(val);
                size_t oidx = (size_t)(row0 + r) * N + (col0 + c);
                if (EPI == 2) {
                    ((float*)Cv)[oidx] = val + R[oidx];
                } else {
                    ((__half*)Cv)[oidx] = __float2half(val);
                }
            }
            __syncwarp();
        }
    }
}

// ---------------- flash attention on packed QKV ---------------------------
// grid (8, 192), 256 threads. K double-buffered; V load overlapped.
#define FLASH_SMEM 212480

__global__ __launch_bounds__(256) void flash_kernel(
    const __half* __restrict__ QKV, __half* __restrict__ Out)
{
    extern __shared__ char fsm[];
    __half* Qs = (__half*)fsm;                 // 128x72 = 18432 B
    __half* Ks = (__half*)(fsm + 18432);       // 2 x 128x72
    __half* Vs = (__half*)(fsm + 55296);       // 128x72
    float*  Ss = (float*)(fsm + 73728);        // 128x132 f32
    __half* Ps = (__half*)(fsm + 141312);      // 128x136 f16
    float*  Cs = (float*)(fsm + 176128);       // 128x68 f32
    float*  mrow = (float*)(fsm + 210944);
    float*  lrow = mrow + 128;
    float*  arow = mrow + 256;

    int z = blockIdx.y, b = z / NH, h = z % NH;
    int rowBase = blockIdx.x * 128;
    const __half* Qb = QKV + (size_t)b * SLEN * QKVN + h * HD;
    const __half* Kb = Qb + EMB;
    const __half* Vb = Qb + 2 * EMB;
    __half* Ob = Out + (size_t)b * SLEN * EMB + h * HD;

    int tid = threadIdx.x, warp = tid >> 5;

    auto loadK = [&](int buf, int kvBase) {
        __half* Kd = Ks + buf * 9216;
        #pragma unroll
        for (int i = 0; i < 4; i++) {
            int idx = tid + i * 256;
            int r = idx >> 3, ch = idx & 7;
            cp16(Kd + r * 72 + ch * 8, Kb + (size_t)(kvBase + r) * QKVN + ch * 8);
        }
    };

    // load Q + K0
    #pragma unroll
    for (int i = 0; i < 4; i++) {
        int idx = tid + i * 256;
        int r = idx >> 3, ch = idx & 7;
        cp16(Qs + r * 72 + ch * 8, Qb + (size_t)(rowBase + r) * QKVN + ch * 8);
    }
    loadK(0, 0);
    CP_COMMIT();
    if (tid < 128) { mrow[tid] = -1e30f; lrow[tid] = 0.0f; }
    #pragma unroll
    for (int i = 0; i < 8; i++) {
        int idx = tid + i * 256;
        int r = idx >> 4, c = (idx & 15) << 2;
        *(float4*)&Cs[r * 68 + c] = make_float4(0.f, 0.f, 0.f, 0.f);
    }
    CP_WAIT(0);
    __syncthreads();

    for (int kt = 0; kt < 8; kt++) {
        int kvBase = kt * 128;
        // issue V(kt) then prefetch K(kt+1); compute QK^T+softmax underneath
        #pragma unroll
        for (int i = 0; i < 4; i++) {
            int idx = tid + i * 256;
            int r = idx >> 3, ch = idx & 7;
            cp16(Vs + r * 72 + ch * 8, Vb + (size_t)(kvBase + r) * QKVN + ch * 8);
        }
        CP_COMMIT();
        if (kt < 7) {
            loadK((kt + 1) & 1, kvBase + 128);
            CP_COMMIT();
        }

        // phase 1: S = Q @ K^T / 8  (2x4 warps, warp tile 64x32)
        {
            __half* Kd = Ks + (kt & 1) * 9216;
            int wr = warp >> 2, wc = warp & 3;
            wmma::fragment<wmma::accumulator, 16, 16, 16, float> acc[4][2];
            #pragma unroll
            for (int f = 0; f < 4; f++)
                #pragma unroll
                for (int g = 0; g < 2; g++) wmma::fill_fragment(acc[f][g], 0.0f);
            #pragma unroll
            for (int kk = 0; kk < HD; kk += 16) {
                wmma::fragment<wmma::matrix_a, 16, 16, 16, __half, wmma::row_major> af[4];
                wmma::fragment<wmma::matrix_b, 16, 16, 16, __half, wmma::col_major> bf[2];
                #pragma unroll
                for (int f = 0; f < 4; f++)
                    wmma::load_matrix_sync(af[f], Qs + (wr * 64 + f * 16) * 72 + kk, 72);
                #pragma unroll
                for (int g = 0; g < 2; g++)
                    wmma::load_matrix_sync(bf[g], Kd + (wc * 32 + g * 16) * 72 + kk, 72);
                #pragma unroll
                for (int f = 0; f < 4; f++)
                    #pragma unroll
                    for (int g = 0; g < 2; g++)
                        wmma::mma_sync(acc[f][g], af[f], bf[g], acc[f][g]);
            }
            #pragma unroll
            for (int f = 0; f < 4; f++)
                #pragma unroll
                for (int g = 0; g < 2; g++) {
                    #pragma unroll
                    for (int e = 0; e < acc[f][g].num_elements; e++)
                        acc[f][g].x[e] *= 0.125f;
                    wmma::store_matrix_sync(
                        Ss + (wr * 64 + f * 16) * 132 + wc * 32 + g * 16,
                        acc[f][g], 132, wmma::mem_row_major);
                }
        }
        __syncthreads();

        // phase 2: online softmax; P -> fp16 Ps
        {
            int r = tid >> 1, half = tid & 1;
            float*  srow = Ss + r * 132 + half * 64;
            __half* prow = Ps + r * 136 + half * 64;
            float mx = -1e30f;
            #pragma unroll
            for (int i = 0; i < 16; i++) {
                float4 v = *(float4*)&srow[i * 4];
                mx = fmaxf(mx, fmaxf(fmaxf(v.x, v.y), fmaxf(v.z, v.w)));
            }
            mx = fmaxf(mx, __shfl_xor_sync(0xFFFFFFFFu, mx, 1));
            float mold = mrow[r];
            float mnew = fmaxf(mold, mx);
            float sum = 0.f;
            #pragma unroll
            for (int i = 0; i < 16; i++) {
                float4 v = *(float4*)&srow[i * 4];
                v.x = __expf(v.x - mnew); v.y = __expf(v.y - mnew);
                v.z = __expf(v.z - mnew); v.w = __expf(v.w - mnew);
                sum += v.x + v.y + v.z + v.w;
                *(__half2*)&prow[i * 4]     = __floats2half2_rn(v.x, v.y);
                *(__half2*)&prow[i * 4 + 2] = __floats2half2_rn(v.z, v.w);
            }
            sum += __shfl_xor_sync(0xFFFFFFFFu, sum, 1);
            if (half == 0) {
                float alpha = __expf(mold - mnew);
                mrow[r] = mnew;
                lrow[r] = lrow[r] * alpha + sum;
                arow[r] = alpha;
            }
        }
        // V must be complete before phase 3
        if (kt < 7) { CP_WAIT(1); } else { CP_WAIT(0); }
        __syncthreads();

        // phase 3: PV = P @ V (4x2 warps, warp tile 32x32); writes Ss
        {
            int wr = warp >> 1, wc = warp & 1;
            wmma::fragment<wmma::accumulator, 16, 16, 16, float> acc[2][2];
            #pragma unroll
            for (int f = 0; f < 2; f++)
                #pragma unroll
                for (int g = 0; g < 2; g++) wmma::fill_fragment(acc[f][g], 0.0f);
            #pragma unroll
            for (int kk = 0; kk < 128; kk += 16) {
                wmma::fragment<wmma::matrix_a, 16, 16, 16, __half, wmma::row_major> af[2];
                wmma::fragment<wmma::matrix_b, 16, 16, 16, __half, wmma::row_major> bf[2];
                #pragma unroll
                for (int f = 0; f < 2; f++)
                    wmma::load_matrix_sync(af[f], Ps + (wr * 32 + f * 16) * 136 + kk, 136);
                #pragma unroll
                for (int g = 0; g < 2; g++)
                    wmma::load_matrix_sync(bf[g], Vs + kk * 72 + wc * 32 + g * 16, 72);
                #pragma unroll
                for (int f = 0; f < 2; f++)
                    #pragma unroll
                    for (int g = 0; g < 2; g++)
                        wmma::mma_sync(acc[f][g], af[f], bf[g], acc[f][g]);
            }
            #pragma unroll
            for (int f = 0; f < 2; f++)
                #pragma unroll
                for (int g = 0; g < 2; g++)
                    wmma::store_matrix_sync(
                        Ss + (wr * 32 + f * 16) * 132 + wc * 32 + g * 16,
                        acc[f][g], 132, wmma::mem_row_major);
        }
        __syncthreads();

        // phase 4: ctx = ctx * alpha + PV
        #pragma unroll
        for (int i = 0; i < 8; i++) {
            int idx = tid + i * 256;
            int r = idx >> 4, c = (idx & 15) << 2;
            float a = arow[r];
            float4 cv = *(float4*)&Cs[r * 68 + c];
            float4 pv = *(float4*)&Ss[r * 132 + c];
            cv.x = cv.x * a + pv.x; cv.y = cv.y * a + pv.y;
            cv.z = cv.z * a + pv.z; cv.w = cv.w * a + pv.w;
            *(float4*)&Cs[r * 68 + c] = cv;
        }
        __syncthreads();
        // ensure K(kt+1) landed before next phase 1
        if (kt < 7) {
            CP_WAIT(0);
            __syncthreads();
        }
    }

    // epilogue: out = ctx / l (fp16)
    #pragma unroll
    for (int i = 0; i < 8; i++) {
        int idx = tid + i * 256;
        int r = idx >> 4, c = (idx & 15) << 2;
        float inv = 1.0f / lrow[r];
        float4 cv = *(float4*)&Cs[r * 68 + c];
        __half* op = Ob + (size_t)(rowBase + r) * EMB + c;
        *(__half2*)op       = __floats2half2_rn(cv.x * inv, cv.y * inv);
        *(__half2*)(op + 2) = __floats2half2_rn(cv.z * inv, cv.w * inv);
    }
}

// ---------------- launch --------------------------------------------------
extern "C" void kernel_launch(void* const* d_in, const int* in_sizes, int n_in,
                              void* d_out, int out_size)
{
    const float* x     = (const float*)d_in[0];
    const float* ln1_g = (const float*)d_in[1];
    const float* ln1_b = (const float*)d_in[2];
    const float* Wq    = (const float*)d_in[3];
    const float* bq    = (const float*)d_in[4];
    const float* Wk    = (const float*)d_in[5];
    const float* bk    = (const float*)d_in[6];
    const float* Wv    = (const float*)d_in[7];
    const float* bv    = (const float*)d_in[8];
    const float* Wo    = (const float*)d_in[9];
    const float* bo    = (const float*)d_in[10];
    const float* ln2_g = (const float*)d_in[11];
    const float* ln2_b = (const float*)d_in[12];
    const float* W1    = (const float*)d_in[13];
    const float* b1    = (const float*)d_in[14];
    const float* W2    = (const float*)d_in[15];
    const float* b2    = (const float*)d_in[16];
    float* out = (float*)d_out;

    __half *pWqkv, *pWo, *pW1, *pW2;
    __half *p_h, *p_qkv, *p_ctx, *p_h2, *p_m1;
    float  *p_x1, *p_bqkv;
    cudaGetSymbolAddress((void**)&pWqkv, hW_qkv);
    cudaGetSymbolAddress((void**)&pWo,   hW_o);
    cudaGetSymbolAddress((void**)&pW1,   hW_1);
    cudaGetSymbolAddress((void**)&pW2,   hW_2);
    cudaGetSymbolAddress((void**)&p_bqkv, g_bqkv);
    cudaGetSymbolAddress((void**)&p_h,   g_h);
    cudaGetSymbolAddress((void**)&p_qkv, g_qkv);
    cudaGetSymbolAddress((void**)&p_ctx, g_ctx);
    cudaGetSymbolAddress((void**)&p_h2,  g_h2);
    cudaGetSymbolAddress((void**)&p_m1,  g_m1);
    cudaGetSymbolAddress((void**)&p_x1,  g_x1);

    cudaFuncSetAttribute(gemm_fp16_kernel<0>, cudaFuncAttributeMaxDynamicSharedMemorySize, GEMM_SMEM);
    cudaFuncSetAttribute(gemm_fp16_kernel<1>, cudaFuncAttributeMaxDynamicSharedMemorySize, GEMM_SMEM);
    cudaFuncSetAttribute(gemm_fp16_kernel<2>, cudaFuncAttributeMaxDynamicSharedMemorySize, GEMM_SMEM);
    cudaFuncSetAttribute(flash_kernel,        cudaFuncAttributeMaxDynamicSharedMemorySize, FLASH_SMEM);

    const int CT = 256;
    packW_kernel<<<(EMB*EMB/4 + CT-1)/CT, CT>>>(Wq, pWqkv, 0);
    packW_kernel<<<(EMB*EMB/4 + CT-1)/CT, CT>>>(Wk, pWqkv, 1);
    packW_kernel<<<(EMB*EMB/4 + CT-1)/CT, CT>>>(Wv, pWqkv, 2);
    packb_kernel<<<(QKVN + CT-1)/CT, CT>>>(bq, bk, bv, p_bqkv);
    f2h_kernel<<<(EMB*EMB/4 + CT-1)/CT, CT>>>(Wo, pWo, EMB*EMB);
    f2h_kernel<<<(EMB*MLPD/4 + CT-1)/CT, CT>>>(W1, pW1, EMB*MLPD);
    f2h_kernel<<<(MLPD*EMB/4 + CT-1)/CT, CT>>>(W2, pW2, MLPD*EMB);

    dim3 gQkv(QKVN / 128, TOKENS / 128);    // (18, 128)
    dim3 gProj(EMB / 128, TOKENS / 128);    // (6, 128)
    dim3 gMlp1(MLPD / 128, TOKENS / 128);   // (24, 128)

    ln_kernel<<<TOKENS, 256>>>(x, ln1_g, ln1_b, p_h);
    gemm_fp16_kernel<0><<<gQkv, 128, GEMM_SMEM>>>(p_h, pWqkv, p_bqkv, nullptr, p_qkv, TOKENS, QKVN, EMB);
    flash_kernel<<<dim3(SLEN / 128, NZ), 256, FLASH_SMEM>>>(p_qkv, p_ctx);
    gemm_fp16_kernel<2><<<gProj, 128, GEMM_SMEM>>>(p_ctx, pWo, bo, x, p_x1, TOKENS, EMB, EMB);
    ln_kernel<<<TOKENS, 256>>>(p_x1, ln2_g, ln2_b, p_h2);
    gemm_fp16_kernel<1><<<gMlp1, 128, GEMM_SMEM>>>(p_h2, pW1, b1, nullptr, p_m1, TOKENS, MLPD, EMB);
    gemm_fp16_kernel<2><<<gProj, 128, GEMM_SMEM>>>(p_m1, pW2, b2, p_x1, out, TOKENS, EMB, MLPD);
}

// round 9
// speedup vs baseline: 4.3450x; 1.1262x over previous
#include <cuda_runtime.h>
#include <cuda_fp16.h>
#include <cstdint>
#include <mma.h>
#include <math.h>

using namespace nvcuda;

#define TOKENS 16384
#define EMB    768
#define NH     12
#define HD     64
#define SLEN   1024
#define BATCH  16
#define MLPD   3072
#define NZ     (BATCH*NH)
#define QKVN   2304

// ---------------- scratch -----------------------------------------------
__device__ __half hW_qkv[EMB*QKVN];
__device__ __half hW_o[EMB*EMB];
__device__ __half hW_1[EMB*MLPD];
__device__ __half hW_2[MLPD*EMB];
__device__ float  g_bqkv[QKVN];
__device__ __half g_h  [TOKENS*EMB];
__device__ __half g_qkv[(size_t)TOKENS*QKVN];
__device__ __half g_ctx[TOKENS*EMB];
__device__ __half g_h2 [TOKENS*EMB];
__device__ __half g_m1 [TOKENS*MLPD];
__device__ float  g_x1 [TOKENS*EMB];

// ---------------- helpers -----------------------------------------------
__device__ __forceinline__ float gelu_exact(float x) {
    return 0.5f * x * (1.0f + erff(x * 0.70710678118654752440f));
}
__device__ __forceinline__ void cp16(void* dst, const void* src) {
    unsigned int s = (unsigned int)__cvta_generic_to_shared(dst);
    asm volatile("cp.async.cg.shared.global [%0], [%1], 16;\n" :: "r"(s), "l"(src));
}
#define CP_COMMIT()  asm volatile("cp.async.commit_group;\n" ::)
#define CP_WAIT(N)   asm volatile("cp.async.wait_group %0;\n" :: "n"(N))

// ---------------- single prep kernel: all weight converts + packs ---------
#define SQ   (EMB*EMB/4)          // 147456 float4 per EMB x EMB matrix
#define SMLP (EMB*MLPD/4)         // 589824 float4 per EMB x MLPD matrix
#define PREP_TOTAL (3*SQ + SQ + 2*SMLP + QKVN/4)

__global__ __launch_bounds__(256) void prep_kernel(
    const float* __restrict__ Wq, const float* __restrict__ Wk,
    const float* __restrict__ Wv, const float* __restrict__ Wo,
    const float* __restrict__ W1, const float* __restrict__ W2,
    const float* __restrict__ bq, const float* __restrict__ bk,
    const float* __restrict__ bv,
    __half* __restrict__ pWqkv, __half* __restrict__ pWo,
    __half* __restrict__ pW1,  __half* __restrict__ pW2,
    float* __restrict__ pbqkv)
{
    int v = blockIdx.x * blockDim.x + threadIdx.x;
    if (v >= PREP_TOTAL) return;
    if (v < 3 * SQ) {
        int which = v / SQ, e = v % SQ;
        const float* W = which == 0 ? Wq : (which == 1 ? Wk : Wv);
        int i = e * 4;
        float4 x = *(const float4*)(W + i);
        int r = i / EMB, c = i % EMB;
        __half* o = pWqkv + (size_t)r * QKVN + which * EMB + c;
        *(__half2*)o       = __floats2half2_rn(x.x, x.y);
        *(__half2*)(o + 2) = __floats2half2_rn(x.z, x.w);
        return;
    }
    v -= 3 * SQ;
    if (v < SQ) {
        int i = v * 4;
        float4 x = *(const float4*)(Wo + i);
        *(__half2*)(pWo + i)     = __floats2half2_rn(x.x, x.y);
        *(__half2*)(pWo + i + 2) = __floats2half2_rn(x.z, x.w);
        return;
    }
    v -= SQ;
    if (v < SMLP) {
        int i = v * 4;
        float4 x = *(const float4*)(W1 + i);
        *(__half2*)(pW1 + i)     = __floats2half2_rn(x.x, x.y);
        *(__half2*)(pW1 + i + 2) = __floats2half2_rn(x.z, x.w);
        return;
    }
    v -= SMLP;
    if (v < SMLP) {
        int i = v * 4;
        float4 x = *(const float4*)(W2 + i);
        *(__half2*)(pW2 + i)     = __floats2half2_rn(x.x, x.y);
        *(__half2*)(pW2 + i + 2) = __floats2half2_rn(x.z, x.w);
        return;
    }
    v -= SMLP;
    {
        int i = v * 4;                 // 0..2300
        int which = i / EMB, j = i % EMB;
        const float* bsrc = which == 0 ? bq : (which == 1 ? bk : bv);
        float4 x = *(const float4*)(bsrc + j);
        *(float4*)(pbqkv + i) = x;
    }
}

// ---------------- LayerNorm (fp32 in, fp16 out) ---------------------------
__global__ __launch_bounds__(256) void ln_kernel(
    const float* __restrict__ x, const float* __restrict__ g,
    const float* __restrict__ b, __half* __restrict__ y)
{
    size_t row = blockIdx.x;
    const float* xr = x + row * EMB;
    int t = threadIdx.x;
    float v0 = xr[t], v1 = xr[t + 256], v2 = xr[t + 512];
    float s  = v0 + v1 + v2;
    float sq = v0*v0 + v1*v1 + v2*v2;
    __shared__ float red0[8], red1[8];
    #pragma unroll
    for (int o = 16; o; o >>= 1) {
        s  += __shfl_xor_sync(0xFFFFFFFFu, s,  o);
        sq += __shfl_xor_sync(0xFFFFFFFFu, sq, o);
    }
    int warp = t >> 5, lane = t & 31;
    if (lane == 0) { red0[warp] = s; red1[warp] = sq; }
    __syncthreads();
    float ts = 0.f, tq = 0.f;
    #pragma unroll
    for (int i = 0; i < 8; i++) { ts += red0[i]; tq += red1[i]; }
    float mu  = ts * (1.0f / EMB);
    float var = tq * (1.0f / EMB) - mu * mu;
    float rs  = rsqrtf(var + 1e-6f);
    __half* yr = y + row * EMB;
    yr[t]       = __float2half((v0 - mu) * rs * g[t]       + b[t]);
    yr[t + 256] = __float2half((v1 - mu) * rs * g[t + 256] + b[t + 256]);
    yr[t + 512] = __float2half((v2 - mu) * rs * g[t + 512] + b[t + 512]);
}

// ---------------- 2-stage BK=64 FP16 GEMM, warp tile 64x64 ----------------
// EPI: 0 bias (half out), 1 bias+gelu (half out), 2 bias+residual (float out)
// stage halves: A 128x72 (9216) + B 64x136 (8704) = 17920 halves = 35840 B; x2
#define GEMM_SMEM 71680

template<int EPI>
__global__ __launch_bounds__(128, 2) void gemm_fp16_kernel(
    const __half* __restrict__ A, const __half* __restrict__ B,
    const float* __restrict__ bias, const float* __restrict__ R,
    void* __restrict__ Cv, int M, int N, int K)
{
    extern __shared__ __half smh[];
    int tid = threadIdx.x;
    int warp = tid >> 5, lane = tid & 31;
    int wr = warp >> 1, wc = warp & 1;
    int rowBase = blockIdx.y * 128;
    int colBase = blockIdx.x * 128;

    wmma::fragment<wmma::accumulator, 16, 16, 16, float> acc[4][4];
    #pragma unroll
    for (int f = 0; f < 4; f++)
        #pragma unroll
        for (int g = 0; g < 4; g++) wmma::fill_fragment(acc[f][g], 0.0f);

    auto load_stage = [&](int s, int k0) {
        __half* As = smh + s * 17920;
        __half* Bs = As + 9216;
        #pragma unroll
        for (int i = 0; i < 8; i++) {           // 1024 chunks of 8 halves
            int idx = tid + i * 128;
            int r = idx >> 3, ch = idx & 7;
            cp16(As + r * 72 + ch * 8, A + (size_t)(rowBase + r) * K + k0 + ch * 8);
        }
        #pragma unroll
        for (int i = 0; i < 8; i++) {           // 1024 chunks
            int idx = tid + i * 128;
            int r = idx >> 4, ch = idx & 15;
            cp16(Bs + r * 136 + ch * 8, B + (size_t)(k0 + r) * N + colBase + ch * 8);
        }
    };

    const int NS = K / 64;
    load_stage(0, 0);
    CP_COMMIT();

    for (int i = 0; i < NS; i++) {
        if (i + 1 < NS) {
            load_stage((i + 1) & 1, (i + 1) * 64);
            CP_COMMIT();
            CP_WAIT(1);
        } else {
            CP_WAIT(0);
        }
        __syncthreads();
        __half* As = smh + (i & 1) * 17920;
        __half* Bs = As + 9216;
        #pragma unroll
        for (int kk = 0; kk < 64; kk += 16) {
            wmma::fragment<wmma::matrix_a, 16, 16, 16, __half, wmma::row_major> af[4];
            wmma::fragment<wmma::matrix_b, 16, 16, 16, __half, wmma::row_major> bf[4];
            #pragma unroll
            for (int f = 0; f < 4; f++)
                wmma::load_matrix_sync(af[f], As + (wr * 64 + f * 16) * 72 + kk, 72);
            #pragma unroll
            for (int g = 0; g < 4; g++)
                wmma::load_matrix_sync(bf[g], Bs + kk * 136 + wc * 64 + g * 16, 136);
            #pragma unroll
            for (int f = 0; f < 4; f++)
                #pragma unroll
                for (int g = 0; g < 4; g++)
                    wmma::mma_sync(acc[f][g], af[f], bf[g], acc[f][g]);
        }
        __syncthreads();
    }

    float* stage = (float*)smh + warp * 320;
    #pragma unroll
    for (int f = 0; f < 4; f++) {
        #pragma unroll
        for (int g = 0; g < 4; g++) {
            wmma::store_matrix_sync(stage, acc[f][g], 20, wmma::mem_row_major);
            __syncwarp();
            int row0 = rowBase + wr * 64 + f * 16;
            int col0 = colBase + wc * 64 + g * 16;
            #pragma unroll
            for (int j = 0; j < 8; j++) {
                int e = lane + j * 32;
                int r = e >> 4, c = e & 15;
                float val = stage[r * 20 + c] + bias[col0 + c];
                if (EPI == 1) val = gelu_exact(val);
                size_t oidx = (size_t)(row0 + r) * N + (col0 + c);
                if (EPI == 2) {
                    ((float*)Cv)[oidx] = val + R[oidx];
                } else {
                    ((__half*)Cv)[oidx] = __float2half(val);
                }
            }
            __syncwarp();
        }
    }
}

// ---------------- flash attention on packed QKV ---------------------------
#define FLASH_SMEM 212480

__global__ __launch_bounds__(256) void flash_kernel(
    const __half* __restrict__ QKV, __half* __restrict__ Out)
{
    extern __shared__ char fsm[];
    __half* Qs = (__half*)fsm;                 // 128x72 = 18432 B
    __half* Ks = (__half*)(fsm + 18432);       // 2 x 128x72
    __half* Vs = (__half*)(fsm + 55296);       // 128x72
    float*  Ss = (float*)(fsm + 73728);        // 128x132 f32
    __half* Ps = (__half*)(fsm + 141312);      // 128x136 f16
    float*  Cs = (float*)(fsm + 176128);       // 128x68 f32
    float*  mrow = (float*)(fsm + 210944);
    float*  lrow = mrow + 128;
    float*  arow = mrow + 256;

    int z = blockIdx.y, b = z / NH, h = z % NH;
    int rowBase = blockIdx.x * 128;
    const __half* Qb = QKV + (size_t)b * SLEN * QKVN + h * HD;
    const __half* Kb = Qb + EMB;
    const __half* Vb = Qb + 2 * EMB;
    __half* Ob = Out + (size_t)b * SLEN * EMB + h * HD;

    int tid = threadIdx.x, warp = tid >> 5;

    auto loadK = [&](int buf, int kvBase) {
        __half* Kd = Ks + buf * 9216;
        #pragma unroll
        for (int i = 0; i < 4; i++) {
            int idx = tid + i * 256;
            int r = idx >> 3, ch = idx & 7;
            cp16(Kd + r * 72 + ch * 8, Kb + (size_t)(kvBase + r) * QKVN + ch * 8);
        }
    };

    #pragma unroll
    for (int i = 0; i < 4; i++) {
        int idx = tid + i * 256;
        int r = idx >> 3, ch = idx & 7;
        cp16(Qs + r * 72 + ch * 8, Qb + (size_t)(rowBase + r) * QKVN + ch * 8);
    }
    loadK(0, 0);
    CP_COMMIT();
    if (tid < 128) { mrow[tid] = -1e30f; lrow[tid] = 0.0f; }
    #pragma unroll
    for (int i = 0; i < 8; i++) {
        int idx = tid + i * 256;
        int r = idx >> 4, c = (idx & 15) << 2;
        *(float4*)&Cs[r * 68 + c] = make_float4(0.f, 0.f, 0.f, 0.f);
    }
    CP_WAIT(0);
    __syncthreads();

    for (int kt = 0; kt < 8; kt++) {
        int kvBase = kt * 128;
        #pragma unroll
        for (int i = 0; i < 4; i++) {
            int idx = tid + i * 256;
            int r = idx >> 3, ch = idx & 7;
            cp16(Vs + r * 72 + ch * 8, Vb + (size_t)(kvBase + r) * QKVN + ch * 8);
        }
        CP_COMMIT();
        if (kt < 7) {
            loadK((kt + 1) & 1, kvBase + 128);
            CP_COMMIT();
        }

        // phase 1: S = Q @ K^T / 8
        {
            __half* Kd = Ks + (kt & 1) * 9216;
            int wr = warp >> 2, wc = warp & 3;
            wmma::fragment<wmma::accumulator, 16, 16, 16, float> acc[4][2];
            #pragma unroll
            for (int f = 0; f < 4; f++)
                #pragma unroll
                for (int g = 0; g < 2; g++) wmma::fill_fragment(acc[f][g], 0.0f);
            #pragma unroll
            for (int kk = 0; kk < HD; kk += 16) {
                wmma::fragment<wmma::matrix_a, 16, 16, 16, __half, wmma::row_major> af[4];
                wmma::fragment<wmma::matrix_b, 16, 16, 16, __half, wmma::col_major> bf[2];
                #pragma unroll
                for (int f = 0; f < 4; f++)
                    wmma::load_matrix_sync(af[f], Qs + (wr * 64 + f * 16) * 72 + kk, 72);
                #pragma unroll
                for (int g = 0; g < 2; g++)
                    wmma::load_matrix_sync(bf[g], Kd + (wc * 32 + g * 16) * 72 + kk, 72);
                #pragma unroll
                for (int f = 0; f < 4; f++)
                    #pragma unroll
                    for (int g = 0; g < 2; g++)
                        wmma::mma_sync(acc[f][g], af[f], bf[g], acc[f][g]);
            }
            #pragma unroll
            for (int f = 0; f < 4; f++)
                #pragma unroll
                for (int g = 0; g < 2; g++) {
                    #pragma unroll
                    for (int e = 0; e < acc[f][g].num_elements; e++)
                        acc[f][g].x[e] *= 0.125f;
                    wmma::store_matrix_sync(
                        Ss + (wr * 64 + f * 16) * 132 + wc * 32 + g * 16,
                        acc[f][g], 132, wmma::mem_row_major);
                }
        }
        __syncthreads();

        // phase 2: online softmax; P -> fp16
        {
            int r = tid >> 1, half = tid & 1;
            float*  srow = Ss + r * 132 + half * 64;
            __half* prow = Ps + r * 136 + half * 64;
            float mx = -1e30f;
            #pragma unroll
            for (int i = 0; i < 16; i++) {
                float4 v = *(float4*)&srow[i * 4];
                mx = fmaxf(mx, fmaxf(fmaxf(v.x, v.y), fmaxf(v.z, v.w)));
            }
            mx = fmaxf(mx, __shfl_xor_sync(0xFFFFFFFFu, mx, 1));
            float mold = mrow[r];
            float mnew = fmaxf(mold, mx);
            float sum = 0.f;
            #pragma unroll
            for (int i = 0; i < 16; i++) {
                float4 v = *(float4*)&srow[i * 4];
                v.x = __expf(v.x - mnew); v.y = __expf(v.y - mnew);
                v.z = __expf(v.z - mnew); v.w = __expf(v.w - mnew);
                sum += v.x + v.y + v.z + v.w;
                *(__half2*)&prow[i * 4]     = __floats2half2_rn(v.x, v.y);
                *(__half2*)&prow[i * 4 + 2] = __floats2half2_rn(v.z, v.w);
            }
            sum += __shfl_xor_sync(0xFFFFFFFFu, sum, 1);
            if (half == 0) {
                float alpha = __expf(mold - mnew);
                mrow[r] = mnew;
                lrow[r] = lrow[r] * alpha + sum;
                arow[r] = alpha;
            }
        }
        if (kt < 7) { CP_WAIT(1); } else { CP_WAIT(0); }
        __syncthreads();

        // phase 3: PV = P @ V
        {
            int wr = warp >> 1, wc = warp & 1;
            wmma::fragment<wmma::accumulator, 16, 16, 16, float> acc[2][2];
            #pragma unroll
            for (int f = 0; f < 2; f++)
                #pragma unroll
                for (int g = 0; g < 2; g++) wmma::fill_fragment(acc[f][g], 0.0f);
            #pragma unroll
            for (int kk = 0; kk < 128; kk += 16) {
                wmma::fragment<wmma::matrix_a, 16, 16, 16, __half, wmma::row_major> af[2];
                wmma::fragment<wmma::matrix_b, 16, 16, 16, __half, wmma::row_major> bf[2];
                #pragma unroll
                for (int f = 0; f < 2; f++)
                    wmma::load_matrix_sync(af[f], Ps + (wr * 32 + f * 16) * 136 + kk, 136);
                #pragma unroll
                for (int g = 0; g < 2; g++)
                    wmma::load_matrix_sync(bf[g], Vs + kk * 72 + wc * 32 + g * 16, 72);
                #pragma unroll
                for (int f = 0; f < 2; f++)
                    #pragma unroll
                    for (int g = 0; g < 2; g++)
                        wmma::mma_sync(acc[f][g], af[f], bf[g], acc[f][g]);
            }
            #pragma unroll
            for (int f = 0; f < 2; f++)
                #pragma unroll
                for (int g = 0; g < 2; g++)
                    wmma::store_matrix_sync(
                        Ss + (wr * 32 + f * 16) * 132 + wc * 32 + g * 16,
                        acc[f][g], 132, wmma::mem_row_major);
        }
        __syncthreads();

        // phase 4: ctx = ctx * alpha + PV
        #pragma unroll
        for (int i = 0; i < 8; i++) {
            int idx = tid + i * 256;
            int r = idx >> 4, c = (idx & 15) << 2;
            float a = arow[r];
            float4 cv = *(float4*)&Cs[r * 68 + c];
            float4 pv = *(float4*)&Ss[r * 132 + c];
            cv.x = cv.x * a + pv.x; cv.y = cv.y * a + pv.y;
            cv.z = cv.z * a + pv.z; cv.w = cv.w * a + pv.w;
            *(float4*)&Cs[r * 68 + c] = cv;
        }
        __syncthreads();
        if (kt < 7) {
            CP_WAIT(0);
            __syncthreads();
        }
    }

    #pragma unroll
    for (int i = 0; i < 8; i++) {
        int idx = tid + i * 256;
        int r = idx >> 4, c = (idx & 15) << 2;
        float inv = 1.0f / lrow[r];
        float4 cv = *(float4*)&Cs[r * 68 + c];
        __half* op = Ob + (size_t)(rowBase + r) * EMB + c;
        *(__half2*)op       = __floats2half2_rn(cv.x * inv, cv.y * inv);
        *(__half2*)(op + 2) = __floats2half2_rn(cv.z * inv, cv.w * inv);
    }
}

// ---------------- launch --------------------------------------------------
extern "C" void kernel_launch(void* const* d_in, const int* in_sizes, int n_in,
                              void* d_out, int out_size)
{
    const float* x     = (const float*)d_in[0];
    const float* ln1_g = (const float*)d_in[1];
    const float* ln1_b = (const float*)d_in[2];
    const float* Wq    = (const float*)d_in[3];
    const float* bq    = (const float*)d_in[4];
    const float* Wk    = (const float*)d_in[5];
    const float* bk    = (const float*)d_in[6];
    const float* Wv    = (const float*)d_in[7];
    const float* bv    = (const float*)d_in[8];
    const float* Wo    = (const float*)d_in[9];
    const float* bo    = (const float*)d_in[10];
    const float* ln2_g = (const float*)d_in[11];
    const float* ln2_b = (const float*)d_in[12];
    const float* W1    = (const float*)d_in[13];
    const float* b1    = (const float*)d_in[14];
    const float* W2    = (const float*)d_in[15];
    const float* b2    = (const float*)d_in[16];
    float* out = (float*)d_out;

    __half *pWqkv, *pWo, *pW1, *pW2;
    __half *p_h, *p_qkv, *p_ctx, *p_h2, *p_m1;
    float  *p_x1, *p_bqkv;
    cudaGetSymbolAddress((void**)&pWqkv, hW_qkv);
    cudaGetSymbolAddress((void**)&pWo,   hW_o);
    cudaGetSymbolAddress((void**)&pW1,   hW_1);
    cudaGetSymbolAddress((void**)&pW2,   hW_2);
    cudaGetSymbolAddress((void**)&p_bqkv, g_bqkv);
    cudaGetSymbolAddress((void**)&p_h,   g_h);
    cudaGetSymbolAddress((void**)&p_qkv, g_qkv);
    cudaGetSymbolAddress((void**)&p_ctx, g_ctx);
    cudaGetSymbolAddress((void**)&p_h2,  g_h2);
    cudaGetSymbolAddress((void**)&p_m1,  g_m1);
    cudaGetSymbolAddress((void**)&p_x1,  g_x1);

    cudaFuncSetAttribute(gemm_fp16_kernel<0>, cudaFuncAttributeMaxDynamicSharedMemorySize, GEMM_SMEM);
    cudaFuncSetAttribute(gemm_fp16_kernel<1>, cudaFuncAttributeMaxDynamicSharedMemorySize, GEMM_SMEM);
    cudaFuncSetAttribute(gemm_fp16_kernel<2>, cudaFuncAttributeMaxDynamicSharedMemorySize, GEMM_SMEM);
    cudaFuncSetAttribute(flash_kernel,        cudaFuncAttributeMaxDynamicSharedMemorySize, FLASH_SMEM);

    prep_kernel<<<(PREP_TOTAL + 255) / 256, 256>>>(
        Wq, Wk, Wv, Wo, W1, W2, bq, bk, bv,
        pWqkv, pWo, pW1, pW2, p_bqkv);

    dim3 gQkv(QKVN / 128, TOKENS / 128);    // (18, 128)
    dim3 gProj(EMB / 128, TOKENS / 128);    // (6, 128)
    dim3 gMlp1(MLPD / 128, TOKENS / 128);   // (24, 128)

    ln_kernel<<<TOKENS, 256>>>(x, ln1_g, ln1_b, p_h);
    gemm_fp16_kernel<0><<<gQkv, 128, GEMM_SMEM>>>(p_h, pWqkv, p_bqkv, nullptr, p_qkv, TOKENS, QKVN, EMB);
    flash_kernel<<<dim3(SLEN / 128, NZ), 256, FLASH_SMEM>>>(p_qkv, p_ctx);
    gemm_fp16_kernel<2><<<gProj, 128, GEMM_SMEM>>>(p_ctx, pWo, bo, x, p_x1, TOKENS, EMB, EMB);
    ln_kernel<<<TOKENS, 256>>>(p_x1, ln2_g, ln2_b, p_h2);
    gemm_fp16_kernel<1><<<gMlp1, 128, GEMM_SMEM>>>(p_h2, pW1, b1, nullptr, p_m1, TOKENS, MLPD, EMB);
    gemm_fp16_kernel<2><<<gProj, 128, GEMM_SMEM>>>(p_m1, pW2, b2, p_x1, out, TOKENS, EMB, MLPD);
}

// round 10
// speedup vs baseline: 5.0475x; 1.1617x over previous
#include <cuda_runtime.h>
#include <cuda_fp16.h>
#include <cstdint>
#include <mma.h>
#include <math.h>

using namespace nvcuda;

#define TOKENS 16384
#define EMB    768
#define NH     12
#define HD     64
#define SLEN   1024
#define BATCH  16
#define MLPD   3072
#define NZ     (BATCH*NH)
#define QKVN   2304

// ---------------- scratch -----------------------------------------------
__device__ __half hW_qkv[EMB*QKVN];
__device__ __half hW_o[EMB*EMB];
__device__ __half hW_1[EMB*MLPD];
__device__ __half hW_2[MLPD*EMB];
__device__ float  g_bqkv[QKVN];
__device__ __half g_h  [TOKENS*EMB];
__device__ __half g_qkv[(size_t)TOKENS*QKVN];
__device__ __half g_ctx[TOKENS*EMB];
__device__ __half g_h2 [TOKENS*EMB];
__device__ __half g_m1 [TOKENS*MLPD];
__device__ float  g_x1 [TOKENS*EMB];

// ---------------- helpers -----------------------------------------------
__device__ __forceinline__ float gelu_exact(float x) {
    return 0.5f * x * (1.0f + erff(x * 0.70710678118654752440f));
}
__device__ __forceinline__ void cp16(void* dst, const void* src) {
    unsigned int s = (unsigned int)__cvta_generic_to_shared(dst);
    asm volatile("cp.async.cg.shared.global [%0], [%1], 16;\n" :: "r"(s), "l"(src));
}
#define CP_COMMIT()  asm volatile("cp.async.commit_group;\n" ::)
#define CP_WAIT(N)   asm volatile("cp.async.wait_group %0;\n" :: "n"(N))

#define MMA16816(d, a0, a1, a2, a3, b0, b1) \
    asm volatile("mma.sync.aligned.m16n8k16.row.col.f32.f16.f16.f32 " \
        "{%0,%1,%2,%3}, {%4,%5,%6,%7}, {%8,%9}, {%0,%1,%2,%3};" \
        : "+f"((d)[0]), "+f"((d)[1]), "+f"((d)[2]), "+f"((d)[3]) \
        : "r"(a0), "r"(a1), "r"(a2), "r"(a3), "r"(b0), "r"(b1))

// ---------------- single prep kernel --------------------------------------
#define SQ   (EMB*EMB/4)
#define SMLP (EMB*MLPD/4)
#define PREP_TOTAL (3*SQ + SQ + 2*SMLP + QKVN/4)

__global__ __launch_bounds__(256) void prep_kernel(
    const float* __restrict__ Wq, const float* __restrict__ Wk,
    const float* __restrict__ Wv, const float* __restrict__ Wo,
    const float* __restrict__ W1, const float* __restrict__ W2,
    const float* __restrict__ bq, const float* __restrict__ bk,
    const float* __restrict__ bv,
    __half* __restrict__ pWqkv, __half* __restrict__ pWo,
    __half* __restrict__ pW1,  __half* __restrict__ pW2,
    float* __restrict__ pbqkv)
{
    int v = blockIdx.x * blockDim.x + threadIdx.x;
    if (v >= PREP_TOTAL) return;
    if (v < 3 * SQ) {
        int which = v / SQ, e = v % SQ;
        const float* W = which == 0 ? Wq : (which == 1 ? Wk : Wv);
        int i = e * 4;
        float4 x = *(const float4*)(W + i);
        int r = i / EMB, c = i % EMB;
        __half* o = pWqkv + (size_t)r * QKVN + which * EMB + c;
        *(__half2*)o       = __floats2half2_rn(x.x, x.y);
        *(__half2*)(o + 2) = __floats2half2_rn(x.z, x.w);
        return;
    }
    v -= 3 * SQ;
    if (v < SQ) {
        int i = v * 4;
        float4 x = *(const float4*)(Wo + i);
        *(__half2*)(pWo + i)     = __floats2half2_rn(x.x, x.y);
        *(__half2*)(pWo + i + 2) = __floats2half2_rn(x.z, x.w);
        return;
    }
    v -= SQ;
    if (v < SMLP) {
        int i = v * 4;
        float4 x = *(const float4*)(W1 + i);
        *(__half2*)(pW1 + i)     = __floats2half2_rn(x.x, x.y);
        *(__half2*)(pW1 + i + 2) = __floats2half2_rn(x.z, x.w);
        return;
    }
    v -= SMLP;
    if (v < SMLP) {
        int i = v * 4;
        float4 x = *(const float4*)(W2 + i);
        *(__half2*)(pW2 + i)     = __floats2half2_rn(x.x, x.y);
        *(__half2*)(pW2 + i + 2) = __floats2half2_rn(x.z, x.w);
        return;
    }
    v -= SMLP;
    {
        int i = v * 4;
        int which = i / EMB, j = i % EMB;
        const float* bsrc = which == 0 ? bq : (which == 1 ? bk : bv);
        float4 x = *(const float4*)(bsrc + j);
        *(float4*)(pbqkv + i) = x;
    }
}

// ---------------- LayerNorm (fp32 in, fp16 out) ---------------------------
__global__ __launch_bounds__(256) void ln_kernel(
    const float* __restrict__ x, const float* __restrict__ g,
    const float* __restrict__ b, __half* __restrict__ y)
{
    size_t row = blockIdx.x;
    const float* xr = x + row * EMB;
    int t = threadIdx.x;
    float v0 = xr[t], v1 = xr[t + 256], v2 = xr[t + 512];
    float s  = v0 + v1 + v2;
    float sq = v0*v0 + v1*v1 + v2*v2;
    __shared__ float red0[8], red1[8];
    #pragma unroll
    for (int o = 16; o; o >>= 1) {
        s  += __shfl_xor_sync(0xFFFFFFFFu, s,  o);
        sq += __shfl_xor_sync(0xFFFFFFFFu, sq, o);
    }
    int warp = t >> 5, lane = t & 31;
    if (lane == 0) { red0[warp] = s; red1[warp] = sq; }
    __syncthreads();
    float ts = 0.f, tq = 0.f;
    #pragma unroll
    for (int i = 0; i < 8; i++) { ts += red0[i]; tq += red1[i]; }
    float mu  = ts * (1.0f / EMB);
    float var = tq * (1.0f / EMB) - mu * mu;
    float rs  = rsqrtf(var + 1e-6f);
    __half* yr = y + row * EMB;
    yr[t]       = __float2half((v0 - mu) * rs * g[t]       + b[t]);
    yr[t + 256] = __float2half((v1 - mu) * rs * g[t + 256] + b[t + 256]);
    yr[t + 512] = __float2half((v2 - mu) * rs * g[t + 512] + b[t + 512]);
}

// ---------------- 2-stage BK=64 FP16 GEMM, warp tile 64x64 ----------------
#define GEMM_SMEM 71680

template<int EPI>
__global__ __launch_bounds__(128, 2) void gemm_fp16_kernel(
    const __half* __restrict__ A, const __half* __restrict__ B,
    const float* __restrict__ bias, const float* __restrict__ R,
    void* __restrict__ Cv, int M, int N, int K)
{
    extern __shared__ __half smh[];
    int tid = threadIdx.x;
    int warp = tid >> 5, lane = tid & 31;
    int wr = warp >> 1, wc = warp & 1;
    int rowBase = blockIdx.y * 128;
    int colBase = blockIdx.x * 128;

    wmma::fragment<wmma::accumulator, 16, 16, 16, float> acc[4][4];
    #pragma unroll
    for (int f = 0; f < 4; f++)
        #pragma unroll
        for (int g = 0; g < 4; g++) wmma::fill_fragment(acc[f][g], 0.0f);

    auto load_stage = [&](int s, int k0) {
        __half* As = smh + s * 17920;
        __half* Bs = As + 9216;
        #pragma unroll
        for (int i = 0; i < 8; i++) {
            int idx = tid + i * 128;
            int r = idx >> 3, ch = idx & 7;
            cp16(As + r * 72 + ch * 8, A + (size_t)(rowBase + r) * K + k0 + ch * 8);
        }
        #pragma unroll
        for (int i = 0; i < 8; i++) {
            int idx = tid + i * 128;
            int r = idx >> 4, ch = idx & 15;
            cp16(Bs + r * 136 + ch * 8, B + (size_t)(k0 + r) * N + colBase + ch * 8);
        }
    };

    const int NS = K / 64;
    load_stage(0, 0);
    CP_COMMIT();

    for (int i = 0; i < NS; i++) {
        if (i + 1 < NS) {
            load_stage((i + 1) & 1, (i + 1) * 64);
            CP_COMMIT();
            CP_WAIT(1);
        } else {
            CP_WAIT(0);
        }
        __syncthreads();
        __half* As = smh + (i & 1) * 17920;
        __half* Bs = As + 9216;
        #pragma unroll
        for (int kk = 0; kk < 64; kk += 16) {
            wmma::fragment<wmma::matrix_a, 16, 16, 16, __half, wmma::row_major> af[4];
            wmma::fragment<wmma::matrix_b, 16, 16, 16, __half, wmma::row_major> bf[4];
            #pragma unroll
            for (int f = 0; f < 4; f++)
                wmma::load_matrix_sync(af[f], As + (wr * 64 + f * 16) * 72 + kk, 72);
            #pragma unroll
            for (int g = 0; g < 4; g++)
                wmma::load_matrix_sync(bf[g], Bs + kk * 136 + wc * 64 + g * 16, 136);
            #pragma unroll
            for (int f = 0; f < 4; f++)
                #pragma unroll
                for (int g = 0; g < 4; g++)
                    wmma::mma_sync(acc[f][g], af[f], bf[g], acc[f][g]);
        }
        __syncthreads();
    }

    float* stage = (float*)smh + warp * 320;
    #pragma unroll
    for (int f = 0; f < 4; f++) {
        #pragma unroll
        for (int g = 0; g < 4; g++) {
            wmma::store_matrix_sync(stage, acc[f][g], 20, wmma::mem_row_major);
            __syncwarp();
            int row0 = rowBase + wr * 64 + f * 16;
            int col0 = colBase + wc * 64 + g * 16;
            #pragma unroll
            for (int j = 0; j < 8; j++) {
                int e = lane + j * 32;
                int r = e >> 4, c = e & 15;
                float val = stage[r * 20 + c] + bias[col0 + c];
                if (EPI == 1) val = gelu_exact(val);
                size_t oidx = (size_t)(row0 + r) * N + (col0 + c);
                if (EPI == 2) {
                    ((float*)Cv)[oidx] = val + R[oidx];
                } else {
                    ((__half*)Cv)[oidx] = __float2half(val);
                }
            }
            __syncwarp();
        }
    }
}

// ---------------- register-resident flash attention -----------------------
// grid (8, 192), 256 threads / 8 warps; each warp owns 16 Q rows.
// smem: K double buf (2x128x72 halves) + V double buf = 73728 B.
#define FLASH_SMEM 73728

__global__ __launch_bounds__(256) void flash_kernel(
    const __half* __restrict__ QKV, __half* __restrict__ Out)
{
    extern __shared__ __half fsh[];
    __half* Ks = fsh;            // 2 x 9216 halves
    __half* Vs = fsh + 18432;    // 2 x 9216 halves

    int z = blockIdx.y, b = z / NH, h = z % NH;
    int rowBase = blockIdx.x * 128;
    const __half* Qb = QKV + (size_t)b * SLEN * QKVN + h * HD;
    const __half* Kb = Qb + EMB;
    const __half* Vb = Qb + 2 * EMB;
    __half* Ob = Out + (size_t)b * SLEN * EMB + h * HD;

    int tid = threadIdx.x, warp = tid >> 5, lane = tid & 31;
    int qr = lane >> 2;          // quad row 0..7
    int qc = (lane & 3) * 2;     // quad col {0,2,4,6}

    auto loadKV = [&](int buf, int kvBase) {
        __half* Kd = Ks + buf * 9216;
        __half* Vd = Vs + buf * 9216;
        #pragma unroll
        for (int i = 0; i < 4; i++) {
            int idx = tid + i * 256;
            int r = idx >> 3, ch = idx & 7;
            cp16(Kd + r * 72 + ch * 8, Kb + (size_t)(kvBase + r) * QKVN + ch * 8);
        }
        #pragma unroll
        for (int i = 0; i < 4; i++) {
            int idx = tid + i * 256;
            int r = idx >> 3, ch = idx & 7;
            cp16(Vd + r * 72 + ch * 8, Vb + (size_t)(kvBase + r) * QKVN + ch * 8);
        }
    };

    // Q fragments direct from global: 4 k-chunks x 4 regs
    uint32_t qa[4][4];
    {
        const __half* q0 = Qb + (size_t)(rowBase + warp * 16 + qr) * QKVN;
        const __half* q8 = q0 + 8 * QKVN;
        #pragma unroll
        for (int kc = 0; kc < 4; kc++) {
            int k0 = kc * 16 + qc;
            qa[kc][0] = *(const uint32_t*)(q0 + k0);
            qa[kc][1] = *(const uint32_t*)(q8 + k0);
            qa[kc][2] = *(const uint32_t*)(q0 + k0 + 8);
            qa[kc][3] = *(const uint32_t*)(q8 + k0 + 8);
        }
    }

    loadKV(0, 0);
    CP_COMMIT();
    loadKV(1, 128);
    CP_COMMIT();

    float m0 = -1e30f, m1 = -1e30f, l0 = 0.f, l1 = 0.f;
    float ctx[8][4];
    #pragma unroll
    for (int n = 0; n < 8; n++) {
        ctx[n][0] = 0.f; ctx[n][1] = 0.f; ctx[n][2] = 0.f; ctx[n][3] = 0.f;
    }

    for (int kt = 0; kt < 8; kt++) {
        if (kt < 7) { CP_WAIT(1); } else { CP_WAIT(0); }
        __syncthreads();
        const __half* Kd = Ks + (kt & 1) * 9216;
        const __half* Vd = Vs + (kt & 1) * 9216;

        // ---- S = Q @ K^T (registers), 16 n-tiles of 8 keys ----
        float s[16][4];
        #pragma unroll
        for (int nt = 0; nt < 16; nt++) {
            s[nt][0] = 0.f; s[nt][1] = 0.f; s[nt][2] = 0.f; s[nt][3] = 0.f;
        }
        #pragma unroll
        for (int kc = 0; kc < 4; kc++) {
            #pragma unroll
            for (int nt = 0; nt < 16; nt++) {
                const __half* kp = Kd + (nt * 8 + qr) * 72 + kc * 16 + qc;
                uint32_t b0 = *(const uint32_t*)kp;
                uint32_t b1 = *(const uint32_t*)(kp + 8);
                MMA16816(s[nt], qa[kc][0], qa[kc][1], qa[kc][2], qa[kc][3], b0, b1);
            }
        }

        // ---- online softmax in registers ----
        float mx0 = -1e30f, mx1 = -1e30f;
        #pragma unroll
        for (int nt = 0; nt < 16; nt++) {
            s[nt][0] *= 0.125f; s[nt][1] *= 0.125f;
            s[nt][2] *= 0.125f; s[nt][3] *= 0.125f;
            mx0 = fmaxf(mx0, fmaxf(s[nt][0], s[nt][1]));
            mx1 = fmaxf(mx1, fmaxf(s[nt][2], s[nt][3]));
        }
        mx0 = fmaxf(mx0, __shfl_xor_sync(0xFFFFFFFFu, mx0, 1));
        mx0 = fmaxf(mx0, __shfl_xor_sync(0xFFFFFFFFu, mx0, 2));
        mx1 = fmaxf(mx1, __shfl_xor_sync(0xFFFFFFFFu, mx1, 1));
        mx1 = fmaxf(mx1, __shfl_xor_sync(0xFFFFFFFFu, mx1, 2));
        float mn0 = fmaxf(m0, mx0), mn1 = fmaxf(m1, mx1);
        float al0 = __expf(m0 - mn0), al1 = __expf(m1 - mn1);
        m0 = mn0; m1 = mn1;

        float sum0 = 0.f, sum1 = 0.f;
        uint32_t pa[8][4];
        #pragma unroll
        for (int nt = 0; nt < 16; nt++) {
            s[nt][0] = __expf(s[nt][0] - m0);
            s[nt][1] = __expf(s[nt][1] - m0);
            s[nt][2] = __expf(s[nt][2] - m1);
            s[nt][3] = __expf(s[nt][3] - m1);
            sum0 += s[nt][0] + s[nt][1];
            sum1 += s[nt][2] + s[nt][3];
        }
        #pragma unroll
        for (int kc = 0; kc < 8; kc++) {
            __half2 h0 = __floats2half2_rn(s[2*kc][0],   s[2*kc][1]);
            __half2 h1 = __floats2half2_rn(s[2*kc][2],   s[2*kc][3]);
            __half2 h2 = __floats2half2_rn(s[2*kc+1][0], s[2*kc+1][1]);
            __half2 h3 = __floats2half2_rn(s[2*kc+1][2], s[2*kc+1][3]);
            pa[kc][0] = *(uint32_t*)&h0; pa[kc][1] = *(uint32_t*)&h1;
            pa[kc][2] = *(uint32_t*)&h2; pa[kc][3] = *(uint32_t*)&h3;
        }
        sum0 += __shfl_xor_sync(0xFFFFFFFFu, sum0, 1);
        sum0 += __shfl_xor_sync(0xFFFFFFFFu, sum0, 2);
        sum1 += __shfl_xor_sync(0xFFFFFFFFu, sum1, 1);
        sum1 += __shfl_xor_sync(0xFFFFFFFFu, sum1, 2);
        l0 = l0 * al0 + sum0;
        l1 = l1 * al1 + sum1;

        #pragma unroll
        for (int n = 0; n < 8; n++) {
            ctx[n][0] *= al0; ctx[n][1] *= al0;
            ctx[n][2] *= al1; ctx[n][3] *= al1;
        }

        // ---- ctx += P @ V ----
        #pragma unroll
        for (int kc = 0; kc < 8; kc++) {
            int kbase = kc * 16;
            #pragma unroll
            for (int nt = 0; nt < 8; nt++) {
                int nidx = nt * 8 + qr;
                const __half* vp = Vd + (kbase + qc) * 72 + nidx;
                __half2 b0h = __halves2half2(vp[0], vp[72]);
                __half2 b1h = __halves2half2(vp[8 * 72], vp[9 * 72]);
                MMA16816(ctx[nt], pa[kc][0], pa[kc][1], pa[kc][2], pa[kc][3],
                         *(uint32_t*)&b0h, *(uint32_t*)&b1h);
            }
        }

        __syncthreads();
        if (kt + 2 < 8) {
            loadKV(kt & 1, (kt + 2) * 128);
            CP_COMMIT();
        }
    }

    // ---- epilogue: out = ctx / l ----
    float inv0 = 1.0f / l0, inv1 = 1.0f / l1;
    __half* o0 = Ob + (size_t)(rowBase + warp * 16 + qr) * EMB + qc;
    __half* o8 = o0 + 8 * EMB;
    #pragma unroll
    for (int nt = 0; nt < 8; nt++) {
        *(__half2*)(o0 + nt * 8) = __floats2half2_rn(ctx[nt][0] * inv0, ctx[nt][1] * inv0);
        *(__half2*)(o8 + nt * 8) = __floats2half2_rn(ctx[nt][2] * inv1, ctx[nt][3] * inv1);
    }
}

// ---------------- launch --------------------------------------------------
extern "C" void kernel_launch(void* const* d_in, const int* in_sizes, int n_in,
                              void* d_out, int out_size)
{
    const float* x     = (const float*)d_in[0];
    const float* ln1_g = (const float*)d_in[1];
    const float* ln1_b = (const float*)d_in[2];
    const float* Wq    = (const float*)d_in[3];
    const float* bq    = (const float*)d_in[4];
    const float* Wk    = (const float*)d_in[5];
    const float* bk    = (const float*)d_in[6];
    const float* Wv    = (const float*)d_in[7];
    const float* bv    = (const float*)d_in[8];
    const float* Wo    = (const float*)d_in[9];
    const float* bo    = (const float*)d_in[10];
    const float* ln2_g = (const float*)d_in[11];
    const float* ln2_b = (const float*)d_in[12];
    const float* W1    = (const float*)d_in[13];
    const float* b1    = (const float*)d_in[14];
    const float* W2    = (const float*)d_in[15];
    const float* b2    = (const float*)d_in[16];
    float* out = (float*)d_out;

    __half *pWqkv, *pWo, *pW1, *pW2;
    __half *p_h, *p_qkv, *p_ctx, *p_h2, *p_m1;
    float  *p_x1, *p_bqkv;
    cudaGetSymbolAddress((void**)&pWqkv, hW_qkv);
    cudaGetSymbolAddress((void**)&pWo,   hW_o);
    cudaGetSymbolAddress((void**)&pW1,   hW_1);
    cudaGetSymbolAddress((void**)&pW2,   hW_2);
    cudaGetSymbolAddress((void**)&p_bqkv, g_bqkv);
    cudaGetSymbolAddress((void**)&p_h,   g_h);
    cudaGetSymbolAddress((void**)&p_qkv, g_qkv);
    cudaGetSymbolAddress((void**)&p_ctx, g_ctx);
    cudaGetSymbolAddress((void**)&p_h2,  g_h2);
    cudaGetSymbolAddress((void**)&p_m1,  g_m1);
    cudaGetSymbolAddress((void**)&p_x1,  g_x1);

    cudaFuncSetAttribute(gemm_fp16_kernel<0>, cudaFuncAttributeMaxDynamicSharedMemorySize, GEMM_SMEM);
    cudaFuncSetAttribute(gemm_fp16_kernel<1>, cudaFuncAttributeMaxDynamicSharedMemorySize, GEMM_SMEM);
    cudaFuncSetAttribute(gemm_fp16_kernel<2>, cudaFuncAttributeMaxDynamicSharedMemorySize, GEMM_SMEM);
    cudaFuncSetAttribute(flash_kernel,        cudaFuncAttributeMaxDynamicSharedMemorySize, FLASH_SMEM);

    prep_kernel<<<(PREP_TOTAL + 255) / 256, 256>>>(
        Wq, Wk, Wv, Wo, W1, W2, bq, bk, bv,
        pWqkv, pWo, pW1, pW2, p_bqkv);

    dim3 gQkv(QKVN / 128, TOKENS / 128);
    dim3 gProj(EMB / 128, TOKENS / 128);
    dim3 gMlp1(MLPD / 128, TOKENS / 128);

    ln_kernel<<<TOKENS, 256>>>(x, ln1_g, ln1_b, p_h);
    gemm_fp16_kernel<0><<<gQkv, 128, GEMM_SMEM>>>(p_h, pWqkv, p_bqkv, nullptr, p_qkv, TOKENS, QKVN, EMB);
    flash_kernel<<<dim3(SLEN / 128, NZ), 256, FLASH_SMEM>>>(p_qkv, p_ctx);
    gemm_fp16_kernel<2><<<gProj, 128, GEMM_SMEM>>>(p_ctx, pWo, bo, x, p_x1, TOKENS, EMB, EMB);
    ln_kernel<<<TOKENS, 256>>>(p_x1, ln2_g, ln2_b, p_h2);
    gemm_fp16_kernel<1><<<gMlp1, 128, GEMM_SMEM>>>(p_h2, pW1, b1, nullptr, p_m1, TOKENS, MLPD, EMB);
    gemm_fp16_kernel<2><<<gProj, 128, GEMM_SMEM>>>(p_m1, pW2, b2, p_x1, out, TOKENS, EMB, MLPD);
}

// round 13
// speedup vs baseline: 5.1903x; 1.0283x over previous
#include <cuda_runtime.h>
#include <cuda_fp16.h>
#include <cstdint>
#include <mma.h>
#include <math.h>

using namespace nvcuda;

#define TOKENS 16384
#define EMB    768
#define NH     12
#define HD     64
#define SLEN   1024
#define BATCH  16
#define MLPD   3072
#define NZ     (BATCH*NH)
#define QKVN   2304

// ---------------- scratch -----------------------------------------------
__device__ __half hW_qkv[EMB*QKVN];
__device__ __half hW_o[EMB*EMB];
__device__ __half hW_1[EMB*MLPD];
__device__ __half hW_2[MLPD*EMB];
__device__ float  g_bqkv[QKVN];
__device__ __half g_h  [TOKENS*EMB];
__device__ __half g_qkv[(size_t)TOKENS*QKVN];
__device__ __half g_ctx[TOKENS*EMB];
__device__ __half g_h2 [TOKENS*EMB];
__device__ __half g_m1 [TOKENS*MLPD];
__device__ float  g_x1 [TOKENS*EMB];

// ---------------- helpers -----------------------------------------------
__device__ __forceinline__ float gelu_exact(float x) {
    return 0.5f * x * (1.0f + erff(x * 0.70710678118654752440f));
}
__device__ __forceinline__ void cp16(void* dst, const void* src) {
    unsigned int s = (unsigned int)__cvta_generic_to_shared(dst);
    asm volatile("cp.async.cg.shared.global [%0], [%1], 16;\n" :: "r"(s), "l"(src));
}
#define CP_COMMIT()  asm volatile("cp.async.commit_group;\n" ::)
#define CP_WAIT(N)   asm volatile("cp.async.wait_group %0;\n" :: "n"(N))

#define MMA16816(d, a0, a1, a2, a3, b0, b1) \
    asm volatile("mma.sync.aligned.m16n8k16.row.col.f32.f16.f16.f32 " \
        "{%0,%1,%2,%3}, {%4,%5,%6,%7}, {%8,%9}, {%0,%1,%2,%3};" \
        : "+f"((d)[0]), "+f"((d)[1]), "+f"((d)[2]), "+f"((d)[3]) \
        : "r"(a0), "r"(a1), "r"(a2), "r"(a3), "r"(b0), "r"(b1))

#define LDSM_X4(r0, r1, r2, r3, addr) \
    asm volatile("ldmatrix.sync.aligned.m8n8.x4.shared.b16 {%0,%1,%2,%3}, [%4];" \
        : "=r"(r0), "=r"(r1), "=r"(r2), "=r"(r3) : "r"(addr))

#define LDSM_X4_T(r0, r1, r2, r3, addr) \
    asm volatile("ldmatrix.sync.aligned.m8n8.x4.trans.shared.b16 {%0,%1,%2,%3}, [%4];" \
        : "=r"(r0), "=r"(r1), "=r"(r2), "=r"(r3) : "r"(addr))

__device__ __forceinline__ uint32_t smem_u32(const void* p) {
    return (uint32_t)__cvta_generic_to_shared(p);
}

// ---------------- single prep kernel --------------------------------------
#define SQ   (EMB*EMB/4)
#define SMLP (EMB*MLPD/4)
#define PREP_TOTAL (3*SQ + SQ + 2*SMLP + QKVN/4)

__global__ __launch_bounds__(256) void prep_kernel(
    const float* __restrict__ Wq, const float* __restrict__ Wk,
    const float* __restrict__ Wv, const float* __restrict__ Wo,
    const float* __restrict__ W1, const float* __restrict__ W2,
    const float* __restrict__ bq, const float* __restrict__ bk,
    const float* __restrict__ bv,
    __half* __restrict__ pWqkv, __half* __restrict__ pWo,
    __half* __restrict__ pW1,  __half* __restrict__ pW2,
    float* __restrict__ pbqkv)
{
    int v = blockIdx.x * blockDim.x + threadIdx.x;
    if (v >= PREP_TOTAL) return;
    if (v < 3 * SQ) {
        int which = v / SQ, e = v % SQ;
        const float* W = which == 0 ? Wq : (which == 1 ? Wk : Wv);
        int i = e * 4;
        float4 x = *(const float4*)(W + i);
        int r = i / EMB, c = i % EMB;
        __half* o = pWqkv + (size_t)r * QKVN + which * EMB + c;
        *(__half2*)o       = __floats2half2_rn(x.x, x.y);
        *(__half2*)(o + 2) = __floats2half2_rn(x.z, x.w);
        return;
    }
    v -= 3 * SQ;
    if (v < SQ) {
        int i = v * 4;
        float4 x = *(const float4*)(Wo + i);
        *(__half2*)(pWo + i)     = __floats2half2_rn(x.x, x.y);
        *(__half2*)(pWo + i + 2) = __floats2half2_rn(x.z, x.w);
        return;
    }
    v -= SQ;
    if (v < SMLP) {
        int i = v * 4;
        float4 x = *(const float4*)(W1 + i);
        *(__half2*)(pW1 + i)     = __floats2half2_rn(x.x, x.y);
        *(__half2*)(pW1 + i + 2) = __floats2half2_rn(x.z, x.w);
        return;
    }
    v -= SMLP;
    if (v < SMLP) {
        int i = v * 4;
        float4 x = *(const float4*)(W2 + i);
        *(__half2*)(pW2 + i)     = __floats2half2_rn(x.x, x.y);
        *(__half2*)(pW2 + i + 2) = __floats2half2_rn(x.z, x.w);
        return;
    }
    v -= SMLP;
    {
        int i = v * 4;
        int which = i / EMB, j = i % EMB;
        const float* bsrc = which == 0 ? bq : (which == 1 ? bk : bv);
        float4 x = *(const float4*)(bsrc + j);
        *(float4*)(pbqkv + i) = x;
    }
}

// ---------------- LayerNorm (fp32 in, fp16 out) ---------------------------
__global__ __launch_bounds__(256) void ln_kernel(
    const float* __restrict__ x, const float* __restrict__ g,
    const float* __restrict__ b, __half* __restrict__ y)
{
    size_t row = blockIdx.x;
    const float* xr = x + row * EMB;
    int t = threadIdx.x;
    float v0 = xr[t], v1 = xr[t + 256], v2 = xr[t + 512];
    float s  = v0 + v1 + v2;
    float sq = v0*v0 + v1*v1 + v2*v2;
    __shared__ float red0[8], red1[8];
    #pragma unroll
    for (int o = 16; o; o >>= 1) {
        s  += __shfl_xor_sync(0xFFFFFFFFu, s,  o);
        sq += __shfl_xor_sync(0xFFFFFFFFu, sq, o);
    }
    int warp = t >> 5, lane = t & 31;
    if (lane == 0) { red0[warp] = s; red1[warp] = sq; }
    __syncthreads();
    float ts = 0.f, tq = 0.f;
    #pragma unroll
    for (int i = 0; i < 8; i++) { ts += red0[i]; tq += red1[i]; }
    float mu  = ts * (1.0f / EMB);
    float var = tq * (1.0f / EMB) - mu * mu;
    float rs  = rsqrtf(var + 1e-6f);
    __half* yr = y + row * EMB;
    yr[t]       = __float2half((v0 - mu) * rs * g[t]       + b[t]);
    yr[t + 256] = __float2half((v1 - mu) * rs * g[t + 256] + b[t + 256]);
    yr[t + 512] = __float2half((v2 - mu) * rs * g[t + 512] + b[t + 512]);
}

// ---------------- 2-stage BK=64 FP16 GEMM, warp tile 64x64 ----------------
#define GEMM_SMEM 71680

template<int EPI>
__global__ __launch_bounds__(128, 2) void gemm_fp16_kernel(
    const __half* __restrict__ A, const __half* __restrict__ B,
    const float* __restrict__ bias, const float* __restrict__ R,
    void* __restrict__ Cv, int M, int N, int K)
{
    extern __shared__ __half smh[];
    int tid = threadIdx.x;
    int warp = tid >> 5, lane = tid & 31;
    int wr = warp >> 1, wc = warp & 1;
    int rowBase = blockIdx.y * 128;
    int colBase = blockIdx.x * 128;

    wmma::fragment<wmma::accumulator, 16, 16, 16, float> acc[4][4];
    #pragma unroll
    for (int f = 0; f < 4; f++)
        #pragma unroll
        for (int g = 0; g < 4; g++) wmma::fill_fragment(acc[f][g], 0.0f);

    auto load_stage = [&](int s, int k0) {
        __half* As = smh + s * 17920;
        __half* Bs = As + 9216;
        #pragma unroll
        for (int i = 0; i < 8; i++) {
            int idx = tid + i * 128;
            int r = idx >> 3, ch = idx & 7;
            cp16(As + r * 72 + ch * 8, A + (size_t)(rowBase + r) * K + k0 + ch * 8);
        }
        #pragma unroll
        for (int i = 0; i < 8; i++) {
            int idx = tid + i * 128;
            int r = idx >> 4, ch = idx & 15;
            cp16(Bs + r * 136 + ch * 8, B + (size_t)(k0 + r) * N + colBase + ch * 8);
        }
    };

    const int NS = K / 64;
    load_stage(0, 0);
    CP_COMMIT();

    for (int i = 0; i < NS; i++) {
        if (i + 1 < NS) {
            load_stage((i + 1) & 1, (i + 1) * 64);
            CP_COMMIT();
            CP_WAIT(1);
        } else {
            CP_WAIT(0);
        }
        __syncthreads();
        __half* As = smh + (i & 1) * 17920;
        __half* Bs = As + 9216;
        #pragma unroll
        for (int kk = 0; kk < 64; kk += 16) {
            wmma::fragment<wmma::matrix_a, 16, 16, 16, __half, wmma::row_major> af[4];
            wmma::fragment<wmma::matrix_b, 16, 16, 16, __half, wmma::row_major> bf[4];
            #pragma unroll
            for (int f = 0; f < 4; f++)
                wmma::load_matrix_sync(af[f], As + (wr * 64 + f * 16) * 72 + kk, 72);
            #pragma unroll
            for (int g = 0; g < 4; g++)
                wmma::load_matrix_sync(bf[g], Bs + kk * 136 + wc * 64 + g * 16, 136);
            #pragma unroll
            for (int f = 0; f < 4; f++)
                #pragma unroll
                for (int g = 0; g < 4; g++)
                    wmma::mma_sync(acc[f][g], af[f], bf[g], acc[f][g]);
        }
        __syncthreads();
    }

    float* stage = (float*)smh + warp * 320;
    #pragma unroll
    for (int f = 0; f < 4; f++) {
        #pragma unroll
        for (int g = 0; g < 4; g++) {
            wmma::store_matrix_sync(stage, acc[f][g], 20, wmma::mem_row_major);
            __syncwarp();
            int row0 = rowBase + wr * 64 + f * 16;
            int col0 = colBase + wc * 64 + g * 16;
            #pragma unroll
            for (int j = 0; j < 8; j++) {
                int e = lane + j * 32;
                int r = e >> 4, c = e & 15;
                float val = stage[r * 20 + c] + bias[col0 + c];
                if (EPI == 1) val = gelu_exact(val);
                size_t oidx = (size_t)(row0 + r) * N + (col0 + c);
                if (EPI == 2) {
                    ((float*)Cv)[oidx] = val + R[oidx];
                } else {
                    ((__half*)Cv)[oidx] = __float2half(val);
                }
            }
            __syncwarp();
        }
    }
}

// ---------------- register-resident flash attention (ldmatrix) ------------
// grid (8, 192), 256 threads / 8 warps; each warp owns 16 Q rows.
#define FLASH_SMEM 73728

__global__ __launch_bounds__(256) void flash_kernel(
    const __half* __restrict__ QKV, __half* __restrict__ Out)
{
    extern __shared__ __half fsh[];
    __half* Ks = fsh;            // 2 x 9216 halves
    __half* Vs = fsh + 18432;    // 2 x 9216 halves

    int z = blockIdx.y, b = z / NH, h = z % NH;
    int rowBase = blockIdx.x * 128;
    const __half* Qb = QKV + (size_t)b * SLEN * QKVN + h * HD;
    const __half* Kb = Qb + EMB;
    const __half* Vb = Qb + 2 * EMB;
    __half* Ob = Out + (size_t)b * SLEN * EMB + h * HD;

    int tid = threadIdx.x, warp = tid >> 5, lane = tid & 31;
    int qr = lane >> 2;          // quad row 0..7
    int qc = (lane & 3) * 2;     // quad col {0,2,4,6}
    int rowin = lane & 7, grp = lane >> 3;
    // K ldmatrix x4 tile mapping: [nt,k+0][nt,k+8][nt+1,k+0][nt+1,k+8]
    int krow = (grp >> 1) * 8 + rowin;   // row within 16-row pair
    int kcol = (grp & 1) * 8;            // k offset within 16
    // V ldmatrix x4.trans tile mapping: [k+0,n+0][k+8,n+0][k+0,n+8][k+8,n+8]
    int vrow = (grp & 1) * 8 + rowin;
    int vcol = (grp >> 1) * 8;

    auto loadKV = [&](int buf, int kvBase) {
        __half* Kd = Ks + buf * 9216;
        __half* Vd = Vs + buf * 9216;
        #pragma unroll
        for (int i = 0; i < 4; i++) {
            int idx = tid + i * 256;
            int r = idx >> 3, ch = idx & 7;
            cp16(Kd + r * 72 + ch * 8, Kb + (size_t)(kvBase + r) * QKVN + ch * 8);
        }
        #pragma unroll
        for (int i = 0; i < 4; i++) {
            int idx = tid + i * 256;
            int r = idx >> 3, ch = idx & 7;
            cp16(Vd + r * 72 + ch * 8, Vb + (size_t)(kvBase + r) * QKVN + ch * 8);
        }
    };

    // Q fragments direct from global: 4 k-chunks x 4 regs
    uint32_t qa[4][4];
    {
        const __half* q0 = Qb + (size_t)(rowBase + warp * 16 + qr) * QKVN;
        const __half* q8 = q0 + 8 * QKVN;
        #pragma unroll
        for (int kc = 0; kc < 4; kc++) {
            int k0 = kc * 16 + qc;
            qa[kc][0] = *(const uint32_t*)(q0 + k0);
            qa[kc][1] = *(const uint32_t*)(q8 + k0);
            qa[kc][2] = *(const uint32_t*)(q0 + k0 + 8);
            qa[kc][3] = *(const uint32_t*)(q8 + k0 + 8);
        }
    }

    loadKV(0, 0);
    CP_COMMIT();
    loadKV(1, 128);
    CP_COMMIT();

    float m0 = -1e30f, m1 = -1e30f, l0 = 0.f, l1 = 0.f;
    float ctx[8][4];
    #pragma unroll
    for (int n = 0; n < 8; n++) {
        ctx[n][0] = 0.f; ctx[n][1] = 0.f; ctx[n][2] = 0.f; ctx[n][3] = 0.f;
    }

    for (int kt = 0; kt < 8; kt++) {
        if (kt < 7) { CP_WAIT(1); } else { CP_WAIT(0); }
        __syncthreads();
        const __half* Kd = Ks + (kt & 1) * 9216;
        const __half* Vd = Vs + (kt & 1) * 9216;
        uint32_t ksb = smem_u32(Kd);
        uint32_t vsb = smem_u32(Vd);

        // ---- S = Q @ K^T via ldmatrix.x4 ----
        float s[16][4];
        #pragma unroll
        for (int nt = 0; nt < 16; nt++) {
            s[nt][0] = 0.f; s[nt][1] = 0.f; s[nt][2] = 0.f; s[nt][3] = 0.f;
        }
        #pragma unroll
        for (int kc = 0; kc < 4; kc++) {
            #pragma unroll
            for (int ntp = 0; ntp < 8; ntp++) {
                uint32_t addr = ksb + ((ntp * 16 + krow) * 72 + kc * 16 + kcol) * 2;
                uint32_t b0, b1, b2, b3;
                LDSM_X4(b0, b1, b2, b3, addr);
                MMA16816(s[2*ntp],   qa[kc][0], qa[kc][1], qa[kc][2], qa[kc][3], b0, b1);
                MMA16816(s[2*ntp+1], qa[kc][0], qa[kc][1], qa[kc][2], qa[kc][3], b2, b3);
            }
        }

        // ---- online softmax in registers ----
        float mx0 = -1e30f, mx1 = -1e30f;
        #pragma unroll
        for (int nt = 0; nt < 16; nt++) {
            s[nt][0] *= 0.125f; s[nt][1] *= 0.125f;
            s[nt][2] *= 0.125f; s[nt][3] *= 0.125f;
            mx0 = fmaxf(mx0, fmaxf(s[nt][0], s[nt][1]));
            mx1 = fmaxf(mx1, fmaxf(s[nt][2], s[nt][3]));
        }
        mx0 = fmaxf(mx0, __shfl_xor_sync(0xFFFFFFFFu, mx0, 1));
        mx0 = fmaxf(mx0, __shfl_xor_sync(0xFFFFFFFFu, mx0, 2));
        mx1 = fmaxf(mx1, __shfl_xor_sync(0xFFFFFFFFu, mx1, 1));
        mx1 = fmaxf(mx1, __shfl_xor_sync(0xFFFFFFFFu, mx1, 2));
        float mn0 = fmaxf(m0, mx0), mn1 = fmaxf(m1, mx1);
        float al0 = __expf(m0 - mn0), al1 = __expf(m1 - mn1);
        m0 = mn0; m1 = mn1;

        float sum0 = 0.f, sum1 = 0.f;
        uint32_t pa[8][4];
        #pragma unroll
        for (int nt = 0; nt < 16; nt++) {
            s[nt][0] = __expf(s[nt][0] - m0);
            s[nt][1] = __expf(s[nt][1] - m0);
            s[nt][2] = __expf(s[nt][2] - m1);
            s[nt][3] = __expf(s[nt][3] - m1);
            sum0 += s[nt][0] + s[nt][1];
            sum1 += s[nt][2] + s[nt][3];
        }
        #pragma unroll
        for (int kc = 0; kc < 8; kc++) {
            __half2 h0 = __floats2half2_rn(s[2*kc][0],   s[2*kc][1]);
            __half2 h1 = __floats2half2_rn(s[2*kc][2],   s[2*kc][3]);
            __half2 h2 = __floats2half2_rn(s[2*kc+1][0], s[2*kc+1][1]);
            __half2 h3 = __floats2half2_rn(s[2*kc+1][2], s[2*kc+1][3]);
            pa[kc][0] = *(uint32_t*)&h0; pa[kc][1] = *(uint32_t*)&h1;
            pa[kc][2] = *(uint32_t*)&h2; pa[kc][3] = *(uint32_t*)&h3;
        }
        sum0 += __shfl_xor_sync(0xFFFFFFFFu, sum0, 1);
        sum0 += __shfl_xor_sync(0xFFFFFFFFu, sum0, 2);
        sum1 += __shfl_xor_sync(0xFFFFFFFFu, sum1, 1);
        sum1 += __shfl_xor_sync(0xFFFFFFFFu, sum1, 2);
        l0 = l0 * al0 + sum0;
        l1 = l1 * al1 + sum1;

        #pragma unroll
        for (int n = 0; n < 8; n++) {
            ctx[n][0] *= al0; ctx[n][1] *= al0;
            ctx[n][2] *= al1; ctx[n][3] *= al1;
        }

        // ---- ctx += P @ V via ldmatrix.x4.trans ----
        #pragma unroll
        for (int kc = 0; kc < 8; kc++) {
            int kbase = kc * 16;
            #pragma unroll
            for (int ntp = 0; ntp < 4; ntp++) {
                uint32_t addr = vsb + ((kbase + vrow) * 72 + ntp * 16 + vcol) * 2;
                uint32_t b0, b1, b2, b3;
                LDSM_X4_T(b0, b1, b2, b3, addr);
                MMA16816(ctx[2*ntp],   pa[kc][0], pa[kc][1], pa[kc][2], pa[kc][3], b0, b1);
                MMA16816(ctx[2*ntp+1], pa[kc][0], pa[kc][1], pa[kc][2], pa[kc][3], b2, b3);
            }
        }

        __syncthreads();
        if (kt + 2 < 8) {
            loadKV(kt & 1, (kt + 2) * 128);
            CP_COMMIT();
        }
    }

    // ---- epilogue: out = ctx / l ----
    float inv0 = 1.0f / l0, inv1 = 1.0f / l1;
    __half* o0 = Ob + (size_t)(rowBase + warp * 16 + qr) * EMB + qc;
    __half* o8 = o0 + 8 * EMB;
    #pragma unroll
    for (int nt = 0; nt < 8; nt++) {
        *(__half2*)(o0 + nt * 8) = __floats2half2_rn(ctx[nt][0] * inv0, ctx[nt][1] * inv0);
        *(__half2*)(o8 + nt * 8) = __floats2half2_rn(ctx[nt][2] * inv1, ctx[nt][3] * inv1);
    }
}

// ---------------- launch --------------------------------------------------
extern "C" void kernel_launch(void* const* d_in, const int* in_sizes, int n_in,
                              void* d_out, int out_size)
{
    const float* x     = (const float*)d_in[0];
    const float* ln1_g = (const float*)d_in[1];
    const float* ln1_b = (const float*)d_in[2];
    const float* Wq    = (const float*)d_in[3];
    const float* bq    = (const float*)d_in[4];
    const float* Wk    = (const float*)d_in[5];
    const float* bk    = (const float*)d_in[6];
    const float* Wv    = (const float*)d_in[7];
    const float* bv    = (const float*)d_in[8];
    const float* Wo    = (const float*)d_in[9];
    const float* bo    = (const float*)d_in[10];
    const float* ln2_g = (const float*)d_in[11];
    const float* ln2_b = (const float*)d_in[12];
    const float* W1    = (const float*)d_in[13];
    const float* b1    = (const float*)d_in[14];
    const float* W2    = (const float*)d_in[15];
    const float* b2    = (const float*)d_in[16];
    float* out = (float*)d_out;

    __half *pWqkv, *pWo, *pW1, *pW2;
    __half *p_h, *p_qkv, *p_ctx, *p_h2, *p_m1;
    float  *p_x1, *p_bqkv;
    cudaGetSymbolAddress((void**)&pWqkv, hW_qkv);
    cudaGetSymbolAddress((void**)&pWo,   hW_o);
    cudaGetSymbolAddress((void**)&pW1,   hW_1);
    cudaGetSymbolAddress((void**)&pW2,   hW_2);
    cudaGetSymbolAddress((void**)&p_bqkv, g_bqkv);
    cudaGetSymbolAddress((void**)&p_h,   g_h);
    cudaGetSymbolAddress((void**)&p_qkv, g_qkv);
    cudaGetSymbolAddress((void**)&p_ctx, g_ctx);
    cudaGetSymbolAddress((void**)&p_h2,  g_h2);
    cudaGetSymbolAddress((void**)&p_m1,  g_m1);
    cudaGetSymbolAddress((void**)&p_x1,  g_x1);

    cudaFuncSetAttribute(gemm_fp16_kernel<0>, cudaFuncAttributeMaxDynamicSharedMemorySize, GEMM_SMEM);
    cudaFuncSetAttribute(gemm_fp16_kernel<1>, cudaFuncAttributeMaxDynamicSharedMemorySize, GEMM_SMEM);
    cudaFuncSetAttribute(gemm_fp16_kernel<2>, cudaFuncAttributeMaxDynamicSharedMemorySize, GEMM_SMEM);
    cudaFuncSetAttribute(flash_kernel,        cudaFuncAttributeMaxDynamicSharedMemorySize, FLASH_SMEM);

    prep_kernel<<<(PREP_TOTAL + 255) / 256, 256>>>(
        Wq, Wk, Wv, Wo, W1, W2, bq, bk, bv,
        pWqkv, pWo, pW1, pW2, p_bqkv);

    dim3 gQkv(QKVN / 128, TOKENS / 128);
    dim3 gProj(EMB / 128, TOKENS / 128);
    dim3 gMlp1(MLPD / 128, TOKENS / 128);

    ln_kernel<<<TOKENS, 256>>>(x, ln1_g, ln1_b, p_h);
    gemm_fp16_kernel<0><<<gQkv, 128, GEMM_SMEM>>>(p_h, pWqkv, p_bqkv, nullptr, p_qkv, TOKENS, QKVN, EMB);
    flash_kernel<<<dim3(SLEN / 128, NZ), 256, FLASH_SMEM>>>(p_qkv, p_ctx);
    gemm_fp16_kernel<2><<<gProj, 128, GEMM_SMEM>>>(p_ctx, pWo, bo, x, p_x1, TOKENS, EMB, EMB);
    ln_kernel<<<TOKENS, 256>>>(p_x1, ln2_g, ln2_b, p_h2);
    gemm_fp16_kernel<1><<<gMlp1, 128, GEMM_SMEM>>>(p_h2, pW1, b1, nullptr, p_m1, TOKENS, MLPD, EMB);
    gemm_fp16_kernel<2><<<gProj, 128, GEMM_SMEM>>>(p_m1, pW2, b2, p_x1, out, TOKENS, EMB, MLPD);
}